// round 14
// baseline (speedup 1.0000x reference)
#include <cuda_runtime.h>
#include <math.h>
#include <stdint.h>

#define Bc 2
#define Cc 128
#define Hc 128
#define Wc 128
#define NBLKc 64
#define BNODc 16
#define Nc 1024
#define NPc 256
#define HWc (Hc*Wc)

#define PROJ_SMEM 176512
#define G64_SMEM  51200
#define ATT_SMEM  52224
#define FUSE_SMEM 52768

// ---------------- scratch ----------------
__device__ float d_Q[Bc*NBLKc*BNODc*NPc];
__device__ float d_feats[Bc*Nc*Cc];
__device__ float d_adjm1[(size_t)Bc*Nc*Nc];   // masked+gated, s=1
__device__ float d_adjm2[(size_t)Bc*Nc*Nc];   // masked+gated, s=2
__device__ float d_diagm[Bc*Nc*16];           // masked+gated diag blocks, s=0
__device__ float d_Xnbr[3*Bc*Nc*Cc];
__device__ float d_Xroot[3*Bc*Nc*Cc];
__device__ float d_egi[3*Bc*Nc];      // exp(-(gi + b_gate[s]))
__device__ float d_egj[3*Bc*Nc];      // exp(-gj)
__device__ float d_convp[(size_t)4*4*Nc*Cc];  // [pair(s-1,b)][kc 0..3][n][c]
__device__ float d_conv[3*Bc*Nc*Cc];
__device__ float d_psum[3*64*Cc];
__device__ float d_psq[3*64*Cc];
__device__ float d_y[3*Bc*Nc*Cc];
__device__ float d_poolp[3*2*16*Cc];
__device__ float d_pools2[3*Bc*Cc];
__device__ float d_yfin[Bc*Nc*Cc];

__device__ __forceinline__ float sigf(float z) { return 1.f/(1.f + __expf(-z)); }

__device__ __forceinline__ uint32_t f2tf32(float v) {
    uint32_t r;
    asm("cvt.rna.tf32.f32 %0, %1;" : "=r"(r) : "f"(v));
    return r;
}
__device__ __forceinline__ void mma_tf32(float* c, const uint32_t* a, const uint32_t* b) {
    asm volatile(
        "mma.sync.aligned.m16n8k8.row.col.f32.tf32.tf32.f32 "
        "{%0,%1,%2,%3}, {%4,%5,%6,%7}, {%8,%9}, {%0,%1,%2,%3};\n"
        : "+f"(c[0]), "+f"(c[1]), "+f"(c[2]), "+f"(c[3])
        : "r"(a[0]), "r"(a[1]), "r"(a[2]), "r"(a[3]), "r"(b[0]), "r"(b[1]));
}

// ==================== projection + fused norm/gates (exp form) ====================
__global__ void k_proj(const float* __restrict__ x, const float* __restrict__ anchor,
                       const float* __restrict__ sigma,
                       const float* __restrict__ wsrc, const float* __restrict__ wdst,
                       const float* __restrict__ bgate)
{
    extern __shared__ float sm[];
    float* pix = sm;                                   // [256][129]
    float* sas = sm + 256*129;                         // [16][257]
    float2* ci = (float2*)(sm + 256*129 + 16*257);     // [16][128]: (isig, anc*isig)
    float* Ss  = (float*)(ci + 16*128);                // [16]
    float* vals = Ss + 16;                             // [16][132]
    float* wsd  = vals + 16*132;                       // [6][128]
    int blk = blockIdx.x, b = blockIdx.y;
    int t = threadIdx.x;
    int bi = blk >> 3, bj = blk & 7;
    int hi = t >> 4, wi = t & 15;

    const float* xb = x + (size_t)b*Cc*HWc + (size_t)(bi*16+hi)*Wc + (bj*16+wi);
    #pragma unroll 8
    for (int c = 0; c < Cc; c++) pix[t*129 + c] = xb[(size_t)c*HWc];

    for (int idx = t; idx < BNODc*Cc; idx += 256) {
        float sr = sigma[blk*BNODc*Cc + idx];
        float isg = 1.f + __expf(-sr);                 // 1/sigmoid(sr)
        float an = anchor[blk*BNODc*Cc + idx];
        ci[idx] = make_float2(isg, an*isg);
    }
    for (int i = t; i < 768; i += 256) wsd[i] = (i < 384) ? wsrc[i] : wdst[i-384];
    __syncthreads();

    float lg[16];
    #pragma unroll
    for (int k = 0; k < 16; k++) lg[k] = 0.f;
    for (int c0 = 0; c0 < Cc; c0 += 16) {
        float px[16];
        #pragma unroll
        for (int cc = 0; cc < 16; cc++) px[cc] = pix[t*129 + c0 + cc];
        #pragma unroll
        for (int k = 0; k < 16; k++) {
            float acc = 0.f;
            #pragma unroll
            for (int cc = 0; cc < 16; cc++) {
                float2 v = ci[k*Cc + c0 + cc];
                float d = fmaf(px[cc], v.x, -v.y);
                acc = fmaf(d, d, acc);
            }
            lg[k] += acc;
        }
    }
    float m = -0.5f*lg[0];
    #pragma unroll
    for (int k = 1; k < 16; k++) m = fmaxf(m, -0.5f*lg[k]);
    float sum = 0.f; float e[16];
    #pragma unroll
    for (int k = 0; k < 16; k++) { e[k] = __expf(-0.5f*lg[k] - m); sum += e[k]; }
    float inv = 1.f/sum;
    #pragma unroll
    for (int k = 0; k < 16; k++) {
        float sv = e[k]*inv;
        sas[k*257 + t] = sv;
        d_Q[(((size_t)b*NBLKc + blk)*BNODc + k)*NPc + t] = sv;
    }
    __syncthreads();

    if (t < 16) {
        float s_ = 0.f;
        for (int p = 0; p < 256; p++) s_ += sas[t*257 + p];
        Ss[t] = s_;
    }
    __syncthreads();

    int c = t & 127, kh = t >> 7;
    #pragma unroll
    for (int kk = 0; kk < 8; kk++) {
        int k = kk*2 + kh;
        float acc = 0.f;
        for (int p = 0; p < 256; p++)
            acc = fmaf(sas[k*257 + p], pix[p*129 + c], acc);
        float2 v = ci[k*Cc + c];
        float S = Ss[k];
        vals[k*132 + c] = (v.x*acc - v.y*S) / (S + 1e-9f);
    }
    __syncthreads();

    int wid = t >> 5, lane = t & 31;
    #pragma unroll
    for (int rr = 0; rr < 2; rr++) {
        int k = wid*2 + rr;
        float r[7] = {0.f,0.f,0.f,0.f,0.f,0.f,0.f};
        #pragma unroll
        for (int q = 0; q < 4; q++) {
            int c2 = lane + q*32;
            float v = vals[k*132 + c2];
            r[0] = fmaf(v, v, r[0]);
            #pragma unroll
            for (int s = 0; s < 3; s++) {
                r[1+s] = fmaf(v, wsd[s*128 + c2], r[1+s]);
                r[4+s] = fmaf(v, wsd[(3+s)*128 + c2], r[4+s]);
            }
        }
        #pragma unroll
        for (int o = 16; o; o >>= 1)
            #pragma unroll
            for (int q = 0; q < 7; q++) r[q] += __shfl_xor_sync(0xffffffffu, r[q], o);
        float ninv = 1.f/fmaxf(sqrtf(r[0]), 1e-12f);
        int grow = b*1024 + blk*16 + k;
        #pragma unroll
        for (int q = 0; q < 4; q++) {
            int c2 = lane + q*32;
            d_feats[(size_t)grow*Cc + c2] = vals[k*132 + c2]*ninv;
        }
        if (lane < 3)
            d_egi[lane*2048 + grow] = __expf(-(r[1+lane]*ninv + bgate[lane]));
        else if (lane >= 4 && lane < 7)
            d_egj[(lane-4)*2048 + grow] = __expf(-r[lane]*ninv);
    }
}

// ==================== adj: tf32 mma GEMM + fused mask/gate emit ====================
// C[64,128] = feats_i[64,128] @ feats_j[128,128]^T; grid (8 jt, 16 it, 2 b)
__global__ void __launch_bounds__(256) k_adj()
{
    __shared__ float As[64*36];     // [m][k]
    __shared__ float Bs[128*36];    // [n][k] (feats rows, direct copy)
    __shared__ float egi0s[64], egi1s[64], egi2s[64];
    __shared__ float egj0s[128], egj1s[128], egj2s[128];
    int t = threadIdx.x;
    int jt = blockIdx.x, it = blockIdx.y, b = blockIdx.z;
    const float* fb = d_feats + (size_t)b*Nc*Cc;
    if (t < 64) {
        egi0s[t] = d_egi[       b*1024 + it*64 + t];
        egi1s[t] = d_egi[2048 + b*1024 + it*64 + t];
        egi2s[t] = d_egi[4096 + b*1024 + it*64 + t];
    } else if (t < 192) {
        int j = t - 64;
        egj0s[j] = d_egj[       b*1024 + jt*128 + j];
        egj1s[j] = d_egj[2048 + b*1024 + jt*128 + j];
        egj2s[j] = d_egj[4096 + b*1024 + jt*128 + j];
    }
    int warp = t >> 5, lane = t & 31;
    int wm = (warp >> 2)*32, wn = (warp & 3)*32;
    int lr = lane >> 2, lc = lane & 3;
    float acc[2][4][4];
    #pragma unroll
    for (int mi = 0; mi < 2; mi++)
        #pragma unroll
        for (int ni = 0; ni < 4; ni++)
            #pragma unroll
            for (int q = 0; q < 4; q++) acc[mi][ni][q] = 0.f;

    int am = t >> 2, ak0 = (t & 3)*8;
    int bn = t >> 1, bk0 = (t & 1)*16;

    for (int ks = 0; ks < 128; ks += 32) {
        __syncthreads();
        {   // A [64][32]
            const float* src = fb + (size_t)(it*64 + am)*Cc + ks + ak0;
            float4 v0 = *(const float4*)src, v1 = *(const float4*)(src + 4);
            float* dst = As + am*36 + ak0;
            dst[0] = __uint_as_float(f2tf32(v0.x)); dst[1] = __uint_as_float(f2tf32(v0.y));
            dst[2] = __uint_as_float(f2tf32(v0.z)); dst[3] = __uint_as_float(f2tf32(v0.w));
            dst[4] = __uint_as_float(f2tf32(v1.x)); dst[5] = __uint_as_float(f2tf32(v1.y));
            dst[6] = __uint_as_float(f2tf32(v1.z)); dst[7] = __uint_as_float(f2tf32(v1.w));
        }
        {   // B [128][32] direct rows
            const float* src = fb + (size_t)(jt*128 + bn)*Cc + ks + bk0;
            float* dst = Bs + bn*36 + bk0;
            #pragma unroll
            for (int q = 0; q < 4; q++) {
                float4 v = *(const float4*)(src + q*4);
                dst[q*4+0] = __uint_as_float(f2tf32(v.x));
                dst[q*4+1] = __uint_as_float(f2tf32(v.y));
                dst[q*4+2] = __uint_as_float(f2tf32(v.z));
                dst[q*4+3] = __uint_as_float(f2tf32(v.w));
            }
        }
        __syncthreads();
        #pragma unroll
        for (int k8 = 0; k8 < 32; k8 += 8) {
            uint32_t afr[2][4];
            #pragma unroll
            for (int mi = 0; mi < 2; mi++) {
                int r = wm + mi*16 + lr;
                afr[mi][0] = __float_as_uint(As[(r  )*36 + k8 + lc    ]);
                afr[mi][1] = __float_as_uint(As[(r+8)*36 + k8 + lc    ]);
                afr[mi][2] = __float_as_uint(As[(r  )*36 + k8 + lc + 4]);
                afr[mi][3] = __float_as_uint(As[(r+8)*36 + k8 + lc + 4]);
            }
            uint32_t bfr[4][2];
            #pragma unroll
            for (int ni = 0; ni < 4; ni++) {
                int n = wn + ni*8 + lr;
                bfr[ni][0] = __float_as_uint(Bs[n*36 + k8 + lc    ]);
                bfr[ni][1] = __float_as_uint(Bs[n*36 + k8 + lc + 4]);
            }
            #pragma unroll
            for (int mi = 0; mi < 2; mi++)
                #pragma unroll
                for (int ni = 0; ni < 4; ni++)
                    mma_tf32(acc[mi][ni], afr[mi], bfr[ni]);
        }
    }
    // epilogue: mask + gate emit
    size_t base = (size_t)b*Nc*Nc;
    #pragma unroll
    for (int mi = 0; mi < 2; mi++) {
        #pragma unroll
        for (int ni = 0; ni < 4; ni++) {
            #pragma unroll
            for (int half = 0; half < 2; half++) {
                int li = wm + mi*16 + lr + half*8;
                int gi = it*64 + li;
                int lj = wn + ni*8 + lc*2;
                int gj = jt*128 + lj;
                float a0 = acc[mi][ni][half*2], a1 = acc[mi][ni][half*2+1];
                bool same = (gi >> 4) == (gj >> 4);
                float m1a = (!same && a0 > 0.5f) ? __fdividef(a0, fmaf(egi1s[li], egj1s[lj], 1.f)) : 0.f;
                float m1b = (!same && a1 > 0.5f) ? __fdividef(a1, fmaf(egi1s[li], egj1s[lj+1], 1.f)) : 0.f;
                float m2a = (a0 > 0.3f) ? __fdividef(a0, fmaf(egi2s[li], egj2s[lj], 1.f)) : 0.f;
                float m2b = (a1 > 0.3f) ? __fdividef(a1, fmaf(egi2s[li], egj2s[lj+1], 1.f)) : 0.f;
                size_t ro = base + (size_t)gi*Nc + gj;
                *(float2*)&d_adjm1[ro] = make_float2(m1a, m1b);
                *(float2*)&d_adjm2[ro] = make_float2(m2a, m2b);
                if (same) {
                    float m0a = (a0 > 0.7f) ? __fdividef(a0, fmaf(egi0s[li], egj0s[lj], 1.f)) : 0.f;
                    float m0b = (a1 > 0.7f) ? __fdividef(a1, fmaf(egi0s[li], egj0s[lj+1], 1.f)) : 0.f;
                    *(float2*)&d_diagm[b*16384 + gi*16 + (gj & 15)] = make_float2(m0a, m0b);
                }
            }
        }
    }
}

// ==================== combined root+nbr GEMM (BM=64, dbuf) ====================
__global__ void __launch_bounds__(256) k_gemm2(const float* __restrict__ Wr, const float* __restrict__ Wn)
{
    extern __shared__ float sm[];
    float* Xs = sm;
    float* Ws = sm + 2*32*68;
    int t = threadIdx.x;
    int y = blockIdx.y; int w = (y >= 3); int s = w ? y-3 : y;
    int row0 = blockIdx.x * 64;
    const float* Wp = (w ? Wn : Wr) + s*Cc*Cc;
    float* Yp = (w ? d_Xnbr : d_Xroot) + (size_t)s*2048*Cc;
    int xr = t >> 2, xk = (t & 3)*8;
    int wk = t >> 3, wc = (t & 7)*16;
    const float* xg = d_feats + (size_t)(row0 + xr)*Cc + xk;
    const float* wg = Wp + (size_t)wk*Cc + wc;
    {
        float4 a0 = *(const float4*)xg, a1 = *(const float4*)(xg+4);
        float* xd = Xs + xr;
        xd[(xk+0)*68]=a0.x; xd[(xk+1)*68]=a0.y; xd[(xk+2)*68]=a0.z; xd[(xk+3)*68]=a0.w;
        xd[(xk+4)*68]=a1.x; xd[(xk+5)*68]=a1.y; xd[(xk+6)*68]=a1.z; xd[(xk+7)*68]=a1.w;
        float* wd = Ws + wk*132 + wc;
        *(float4*)(wd  ) = *(const float4*)(wg  );
        *(float4*)(wd+4) = *(const float4*)(wg+4);
        *(float4*)(wd+8) = *(const float4*)(wg+8);
        *(float4*)(wd+12)= *(const float4*)(wg+12);
    }
    __syncthreads();
    int tx = t & 31, ty = t >> 5;
    float acc[8][4] = {};
    #pragma unroll
    for (int kb = 0; kb < 4; kb++) {
        int buf = kb & 1;
        float4 pa0, pa1, pw0, pw1, pw2, pw3;
        if (kb < 3) {
            pa0 = *(const float4*)(xg + (kb+1)*32);
            pa1 = *(const float4*)(xg + (kb+1)*32 + 4);
            const float* wn = wg + (size_t)(kb+1)*32*Cc;
            pw0 = *(const float4*)(wn); pw1 = *(const float4*)(wn+4);
            pw2 = *(const float4*)(wn+8); pw3 = *(const float4*)(wn+12);
        }
        const float* Xb = Xs + buf*(32*68);
        const float* Wb = Ws + buf*(32*132);
        #pragma unroll
        for (int k = 0; k < 32; k++) {
            float4 a0 = *(const float4*)&Xb[k*68 + ty*8];
            float4 a1 = *(const float4*)&Xb[k*68 + ty*8 + 4];
            float4 bv = *(const float4*)&Wb[k*132 + tx*4];
            float aa[8] = {a0.x,a0.y,a0.z,a0.w,a1.x,a1.y,a1.z,a1.w};
            float bb[4] = {bv.x,bv.y,bv.z,bv.w};
            #pragma unroll
            for (int i = 0; i < 8; i++)
                #pragma unroll
                for (int j = 0; j < 4; j++)
                    acc[i][j] = fmaf(aa[i], bb[j], acc[i][j]);
        }
        if (kb < 3) {
            int nb = buf ^ 1;
            float* xd = Xs + nb*(32*68) + xr;
            xd[(xk+0)*68]=pa0.x; xd[(xk+1)*68]=pa0.y; xd[(xk+2)*68]=pa0.z; xd[(xk+3)*68]=pa0.w;
            xd[(xk+4)*68]=pa1.x; xd[(xk+5)*68]=pa1.y; xd[(xk+6)*68]=pa1.z; xd[(xk+7)*68]=pa1.w;
            float* wd = Ws + nb*(32*132) + wk*132 + wc;
            *(float4*)(wd  ) = pw0; *(float4*)(wd+4) = pw1;
            *(float4*)(wd+8) = pw2; *(float4*)(wd+12)= pw3;
            __syncthreads();
        }
    }
    #pragma unroll
    for (int i = 0; i < 8; i++) {
        int r = row0 + ty*8 + i;
        *(float4*)&Yp[(size_t)r*Cc + tx*4]
            = make_float4(acc[i][0],acc[i][1],acc[i][2],acc[i][3]);
    }
}

// ==================== s=1,2 aggregation: tf32 mma, BM=32 for occupancy ====================
// C[32,128] += A[32,256] @ B[256,128]; grid (32 m, 4 pair, 4 kc) = 512 blocks
__global__ void __launch_bounds__(256) k_agg()
{
    __shared__ float As[32*36];
    __shared__ float Bs[128*36];
    int t = threadIdx.x;
    int i0 = blockIdx.x * 32;
    int y = blockIdx.y;
    int s = 1 + (y >> 1), b = y & 1;
    int kc = blockIdx.z;
    size_t fb = ((size_t)s*2048 + b*1024)*Cc;
    const float* Asrc = (s == 1 ? d_adjm1 : d_adjm2) + (size_t)b*Nc*Nc;
    int warp = t >> 5, lane = t & 31;
    int wm = (warp >> 2)*16, wn = (warp & 3)*32;
    int lr = lane >> 2, lc = lane & 3;
    float acc[4][4];
    #pragma unroll
    for (int ni = 0; ni < 4; ni++)
        #pragma unroll
        for (int q = 0; q < 4; q++) acc[ni][q] = 0.f;

    int am = t >> 3, ak0 = (t & 7)*4;       // A: 1 float4/thread
    int bj = t & 31, bc0 = (t >> 5)*16;     // B transpose stage

    for (int ks = 0; ks < 256; ks += 32) {
        __syncthreads();
        {
            const float* src = Asrc + (size_t)(i0 + am)*Nc + kc*256 + ks + ak0;
            float4 v = *(const float4*)src;
            float* dst = As + am*36 + ak0;
            dst[0] = __uint_as_float(f2tf32(v.x)); dst[1] = __uint_as_float(f2tf32(v.y));
            dst[2] = __uint_as_float(f2tf32(v.z)); dst[3] = __uint_as_float(f2tf32(v.w));
        }
        {
            const float* src = d_Xnbr + fb + (size_t)(kc*256 + ks + bj)*Cc + bc0;
            #pragma unroll
            for (int q = 0; q < 4; q++) {
                float4 v = *(const float4*)(src + q*4);
                int cb = bc0 + q*4;
                Bs[(cb+0)*36 + bj] = __uint_as_float(f2tf32(v.x));
                Bs[(cb+1)*36 + bj] = __uint_as_float(f2tf32(v.y));
                Bs[(cb+2)*36 + bj] = __uint_as_float(f2tf32(v.z));
                Bs[(cb+3)*36 + bj] = __uint_as_float(f2tf32(v.w));
            }
        }
        __syncthreads();
        #pragma unroll
        for (int k8 = 0; k8 < 32; k8 += 8) {
            uint32_t afr[4];
            {
                int r = wm + lr;
                afr[0] = __float_as_uint(As[(r  )*36 + k8 + lc    ]);
                afr[1] = __float_as_uint(As[(r+8)*36 + k8 + lc    ]);
                afr[2] = __float_as_uint(As[(r  )*36 + k8 + lc + 4]);
                afr[3] = __float_as_uint(As[(r+8)*36 + k8 + lc + 4]);
            }
            uint32_t bfr[4][2];
            #pragma unroll
            for (int ni = 0; ni < 4; ni++) {
                int n = wn + ni*8 + lr;
                bfr[ni][0] = __float_as_uint(Bs[n*36 + k8 + lc    ]);
                bfr[ni][1] = __float_as_uint(Bs[n*36 + k8 + lc + 4]);
            }
            #pragma unroll
            for (int ni = 0; ni < 4; ni++)
                mma_tf32(acc[ni], afr, bfr[ni]);
        }
    }
    size_t pb = (size_t)y*524288 + (size_t)kc*131072;
    #pragma unroll
    for (int ni = 0; ni < 4; ni++) {
        int r0 = i0 + wm + lr;
        int col = wn + ni*8 + lc*2;
        *(float2*)&d_convp[pb + (size_t)r0*Cc + col] = make_float2(acc[ni][0], acc[ni][1]);
        *(float2*)&d_convp[pb + (size_t)(r0+8)*Cc + col] = make_float2(acc[ni][2], acc[ni][3]);
    }
}

// ==================== combine partials + BN partial stats (+ s=0 diag agg) ====================
__global__ void k_comb()
{
    int s = blockIdx.x, part = blockIdx.y, t = threadIdx.x;
    float su = 0.f, sq = 0.f;
    int rbase = part*32;
    if (s == 0) {
        __shared__ float Xn[32][129];
        __shared__ float Am[2][16][17];
        int b = rbase >> 10, n0 = rbase & 1023;
        #pragma unroll
        for (int j2 = 0; j2 < 32; j2++)
            Xn[j2][t] = d_Xnbr[((size_t)b*1024 + n0 + j2)*Cc + t];
        #pragma unroll
        for (int l = 0; l < 4; l++) {
            int id = t + l*128;
            int lb = id >> 8, i = (id >> 4) & 15, j = id & 15;
            Am[lb][i][j] = d_diagm[b*16384 + (n0 + lb*16 + i)*16 + j];
        }
        __syncthreads();
        for (int r0 = 0; r0 < 32; r0++) {
            int rr = rbase + r0;
            int lb = r0 >> 4, i = r0 & 15;
            size_t ci = (size_t)rr*Cc + t;
            float v = d_Xroot[ci];
            #pragma unroll
            for (int j = 0; j < 16; j++)
                v = fmaf(Am[lb][i][j], Xn[lb*16 + j][t], v);
            d_conv[ci] = v;
            su += v; sq = fmaf(v, v, sq);
        }
    } else {
        for (int r0 = 0; r0 < 32; r0++) {
            int rr = rbase + r0;
            size_t ci = ((size_t)s*2048 + rr)*Cc + t;
            int b = rr >> 10, n = rr & 1023;
            size_t pbb = ((size_t)(s-1)*2 + b)*524288 + (size_t)n*Cc + t;
            float v = d_Xroot[ci] + d_convp[pbb] + d_convp[pbb + 131072]
                    + d_convp[pbb + 262144] + d_convp[pbb + 393216];
            d_conv[ci] = v;
            su += v; sq = fmaf(v, v, sq);
        }
    }
    d_psum[(s*64 + part)*Cc + t] = su;
    d_psq [(s*64 + part)*Cc + t] = sq;
}

// ==================== att GEMM ====================
__global__ void __launch_bounds__(256) k_attgemm(const float* __restrict__ attW, const float* __restrict__ attb,
                          const float* __restrict__ gamma, const float* __restrict__ beta)
{
    extern __shared__ float sm[];
    float* Xs = sm;
    float* Ws = sm + 2*32*68;
    float* scl = sm + 12800;
    float* sft = scl + 128;
    int t = threadIdx.x;
    int row0 = blockIdx.x * 64;
    int s = row0 >> 11;
    if (t < 128) {
        float su = 0.f, sq = 0.f;
        #pragma unroll 8
        for (int p = 0; p < 64; p++) {
            su += d_psum[(s*64+p)*Cc + t];
            sq += d_psq [(s*64+p)*Cc + t];
        }
        float mu = su / 2048.f;
        float va = sq / 2048.f - mu*mu;
        float sc = gamma[s*Cc + t]*rsqrtf(va + 1e-5f);
        scl[t] = sc;
        sft[t] = beta[s*Cc + t] - mu*sc;
    }
    __syncthreads();
    const float* Wp = attW + s*Cc*Cc;
    int xr = t >> 2, xk = (t & 3)*8;
    int wk = t >> 3, wc = (t & 7)*16;
    int fr = (row0 + xr) & 2047;
    const float* cg = d_conv + (size_t)(row0 + xr)*Cc + xk;
    const float* fg = d_feats + (size_t)fr*Cc + xk;
    const float* wg = Wp + (size_t)wk*Cc + wc;
    {
        float4 c0 = *(const float4*)cg, c1 = *(const float4*)(cg+4);
        float4 f0 = *(const float4*)fg, f1 = *(const float4*)(fg+4);
        float* xd = Xs + xr;
        xd[(xk+0)*68] = c0.x*scl[xk+0]+sft[xk+0]+f0.x;
        xd[(xk+1)*68] = c0.y*scl[xk+1]+sft[xk+1]+f0.y;
        xd[(xk+2)*68] = c0.z*scl[xk+2]+sft[xk+2]+f0.z;
        xd[(xk+3)*68] = c0.w*scl[xk+3]+sft[xk+3]+f0.w;
        xd[(xk+4)*68] = c1.x*scl[xk+4]+sft[xk+4]+f1.x;
        xd[(xk+5)*68] = c1.y*scl[xk+5]+sft[xk+5]+f1.y;
        xd[(xk+6)*68] = c1.z*scl[xk+6]+sft[xk+6]+f1.z;
        xd[(xk+7)*68] = c1.w*scl[xk+7]+sft[xk+7]+f1.w;
        float* wd = Ws + wk*132 + wc;
        *(float4*)(wd  ) = *(const float4*)(wg  );
        *(float4*)(wd+4) = *(const float4*)(wg+4);
        *(float4*)(wd+8) = *(const float4*)(wg+8);
        *(float4*)(wd+12)= *(const float4*)(wg+12);
    }
    __syncthreads();
    int tx = t & 31, ty = t >> 5;
    float acc[8][4] = {};
    #pragma unroll
    for (int kb = 0; kb < 4; kb++) {
        int buf = kb & 1;
        float4 pc0, pc1, pf0, pf1, pw0, pw1, pw2, pw3;
        if (kb < 3) {
            pc0 = *(const float4*)(cg + (kb+1)*32);
            pc1 = *(const float4*)(cg + (kb+1)*32 + 4);
            pf0 = *(const float4*)(fg + (kb+1)*32);
            pf1 = *(const float4*)(fg + (kb+1)*32 + 4);
            const float* wn = wg + (size_t)(kb+1)*32*Cc;
            pw0 = *(const float4*)(wn); pw1 = *(const float4*)(wn+4);
            pw2 = *(const float4*)(wn+8); pw3 = *(const float4*)(wn+12);
        }
        const float* Xb = Xs + buf*(32*68);
        const float* Wb = Ws + buf*(32*132);
        #pragma unroll
        for (int k = 0; k < 32; k++) {
            float4 a0 = *(const float4*)&Xb[k*68 + ty*8];
            float4 a1 = *(const float4*)&Xb[k*68 + ty*8 + 4];
            float4 bv = *(const float4*)&Wb[k*132 + tx*4];
            float aa[8] = {a0.x,a0.y,a0.z,a0.w,a1.x,a1.y,a1.z,a1.w};
            float bb[4] = {bv.x,bv.y,bv.z,bv.w};
            #pragma unroll
            for (int i = 0; i < 8; i++)
                #pragma unroll
                for (int j = 0; j < 4; j++)
                    acc[i][j] = fmaf(aa[i], bb[j], acc[i][j]);
        }
        if (kb < 3) {
            int nb = buf ^ 1;
            int kbase = (kb+1)*32;
            float* xd = Xs + nb*(32*68) + xr;
            xd[(xk+0)*68] = pc0.x*scl[kbase+xk+0]+sft[kbase+xk+0]+pf0.x;
            xd[(xk+1)*68] = pc0.y*scl[kbase+xk+1]+sft[kbase+xk+1]+pf0.y;
            xd[(xk+2)*68] = pc0.z*scl[kbase+xk+2]+sft[kbase+xk+2]+pf0.z;
            xd[(xk+3)*68] = pc0.w*scl[kbase+xk+3]+sft[kbase+xk+3]+pf0.w;
            xd[(xk+4)*68] = pc1.x*scl[kbase+xk+4]+sft[kbase+xk+4]+pf1.x;
            xd[(xk+5)*68] = pc1.y*scl[kbase+xk+5]+sft[kbase+xk+5]+pf1.y;
            xd[(xk+6)*68] = pc1.z*scl[kbase+xk+6]+sft[kbase+xk+6]+pf1.z;
            xd[(xk+7)*68] = pc1.w*scl[kbase+xk+7]+sft[kbase+xk+7]+pf1.w;
            float* wd = Ws + nb*(32*132) + wk*132 + wc;
            *(float4*)(wd  ) = pw0; *(float4*)(wd+4) = pw1;
            *(float4*)(wd+8) = pw2; *(float4*)(wd+12)= pw3;
            __syncthreads();
        }
    }
    float colmax[4] = {-3.4e38f,-3.4e38f,-3.4e38f,-3.4e38f};
    #pragma unroll
    for (int i = 0; i < 8; i++) {
        int row = row0 + ty*8 + i;
        int frr = row & 2047;
        float4 cv = *(const float4*)&d_conv[(size_t)row*Cc + tx*4];
        float4 fv = *(const float4*)&d_feats[(size_t)frr*Cc + tx*4];
        float cva[4] = {cv.x,cv.y,cv.z,cv.w};
        float fva[4] = {fv.x,fv.y,fv.z,fv.w};
        float o[4];
        #pragma unroll
        for (int j = 0; j < 4; j++) {
            int c = tx*4 + j;
            float v = acc[i][j] + attb[s*Cc + c];
            float hv = cva[j]*scl[c] + sft[c] + fva[j];
            float yv = fmaxf(sigf(v)*hv, 0.f);
            o[j] = yv;
            colmax[j] = fmaxf(colmax[j], yv);
        }
        *(float4*)&d_y[(size_t)row*Cc + tx*4] = make_float4(o[0],o[1],o[2],o[3]);
    }
    __syncthreads();
    float* pm = sm;
    #pragma unroll
    for (int j = 0; j < 4; j++) pm[ty*132 + tx*4 + j] = colmax[j];
    __syncthreads();
    if (t < 128) {
        float m = -3.4e38f;
        #pragma unroll
        for (int q = 0; q < 8; q++) m = fmaxf(m, pm[q*132 + t]);
        int bb = (row0 >> 10) & 1, tl = (row0 & 1023) >> 6;
        d_poolp[((s*2 + bb)*16 + tl)*Cc + t] = m;
    }
}

// ==================== mlp ====================
__global__ void k_mlp(const float* __restrict__ W1, const float* __restrict__ b1,
                      const float* __restrict__ W2, const float* __restrict__ b2)
{
    int sb = blockIdx.x, t = threadIdx.x;
    int s = sb >> 1;
    __shared__ float p[128], t1[128];
    float m = -3.4e38f;
    #pragma unroll
    for (int ch = 0; ch < 16; ch++) m = fmaxf(m, d_poolp[(sb*16 + ch)*Cc + t]);
    p[t] = m;
    __syncthreads();
    float acc = b1[s*Cc + t];
    #pragma unroll 8
    for (int k = 0; k < 128; k++) acc = fmaf(p[k], W1[s*Cc*Cc + k*Cc + t], acc);
    t1[t] = fmaxf(acc, 0.f);
    __syncthreads();
    float acc2 = b2[s*Cc + t];
    #pragma unroll 8
    for (int k = 0; k < 128; k++) acc2 = fmaf(t1[k], W2[s*Cc*Cc + k*Cc + t], acc2);
    d_pools2[sb*Cc + t] = sigf(acc2);
}

// ==================== final GEMM: fused softmax-mix X + Aw prologue ====================
__global__ void __launch_bounds__(256) k_fusegemm(const float* __restrict__ W, const float* __restrict__ bias,
                           const float* __restrict__ lw, const float* __restrict__ lb)
{
    extern __shared__ float sm[];
    float* Xs = sm;
    float* Ws = sm + 2*32*68;
    float* p2s = sm + 12800;
    float* aw  = p2s + 384;
    int t = threadIdx.x;
    int row0 = blockIdx.x * 64;
    int b = row0 >> 10;
    for (int i = t; i < 384; i += 256)
        p2s[i] = d_pools2[((i >> 7)*2 + b)*Cc + (i & 127)];
    __syncthreads();
    if (t < 32) {
        float av[3];
        #pragma unroll
        for (int s = 0; s < 3; s++) {
            float r = 0.f;
            #pragma unroll
            for (int q = 0; q < 4; q++) {
                int c = t + q*32;
                r = fmaf(p2s[s*128 + c], lw[s*Cc + c], r);
            }
            #pragma unroll
            for (int o = 16; o; o >>= 1) r += __shfl_xor_sync(0xffffffffu, r, o);
            av[s] = r + lb[s];
        }
        if (t == 0) {
            float m = fmaxf(av[0], fmaxf(av[1], av[2]));
            float e0 = __expf(av[0]-m), e1 = __expf(av[1]-m), e2 = __expf(av[2]-m);
            float inv = 1.f/(e0+e1+e2);
            aw[0] = e0*inv; aw[1] = e1*inv; aw[2] = e2*inv;
        }
    }
    __syncthreads();
    float aw0 = aw[0], aw1 = aw[1], aw2 = aw[2];
    int xr = t >> 2, xk = (t & 3)*8;
    int wk = t >> 3, wc = (t & 7)*16;
    const float* y0 = d_y + (size_t)(row0 + xr)*Cc + xk;
    const float* y1 = y0 + (size_t)2048*Cc;
    const float* y2 = y1 + (size_t)2048*Cc;
    const float* wg = W + (size_t)wk*Cc + wc;
    #define FUSE_XLOAD(dst, off) { \
        float4 v0 = *(const float4*)(y0+(off)), v0b = *(const float4*)(y0+(off)+4); \
        float4 v1 = *(const float4*)(y1+(off)), v1b = *(const float4*)(y1+(off)+4); \
        float4 v2 = *(const float4*)(y2+(off)), v2b = *(const float4*)(y2+(off)+4); \
        int kb0 = (off) + xk; \
        dst[(xk+0)*68] = aw0*p2s[kb0+0]*v0.x + aw1*p2s[128+kb0+0]*v1.x + aw2*p2s[256+kb0+0]*v2.x; \
        dst[(xk+1)*68] = aw0*p2s[kb0+1]*v0.y + aw1*p2s[128+kb0+1]*v1.y + aw2*p2s[256+kb0+1]*v2.y; \
        dst[(xk+2)*68] = aw0*p2s[kb0+2]*v0.z + aw1*p2s[128+kb0+2]*v1.z + aw2*p2s[256+kb0+2]*v2.z; \
        dst[(xk+3)*68] = aw0*p2s[kb0+3]*v0.w + aw1*p2s[128+kb0+3]*v1.w + aw2*p2s[256+kb0+3]*v2.w; \
        dst[(xk+4)*68] = aw0*p2s[kb0+4]*v0b.x + aw1*p2s[128+kb0+4]*v1b.x + aw2*p2s[256+kb0+4]*v2b.x; \
        dst[(xk+5)*68] = aw0*p2s[kb0+5]*v0b.y + aw1*p2s[128+kb0+5]*v1b.y + aw2*p2s[256+kb0+5]*v2b.y; \
        dst[(xk+6)*68] = aw0*p2s[kb0+6]*v0b.z + aw1*p2s[128+kb0+6]*v1b.z + aw2*p2s[256+kb0+6]*v2b.z; \
        dst[(xk+7)*68] = aw0*p2s[kb0+7]*v0b.w + aw1*p2s[128+kb0+7]*v1b.w + aw2*p2s[256+kb0+7]*v2b.w; \
    }
    {
        float* xd = Xs + xr;
        FUSE_XLOAD(xd, 0);
        float* wd = Ws + wk*132 + wc;
        *(float4*)(wd  ) = *(const float4*)(wg  );
        *(float4*)(wd+4) = *(const float4*)(wg+4);
        *(float4*)(wd+8) = *(const float4*)(wg+8);
        *(float4*)(wd+12)= *(const float4*)(wg+12);
    }
    __syncthreads();
    int tx = t & 31, ty = t >> 5;
    float acc[8][4] = {};
    #pragma unroll
    for (int kb = 0; kb < 4; kb++) {
        int buf = kb & 1;
        const float* Xb = Xs + buf*(32*68);
        const float* Wb = Ws + buf*(32*132);
        #pragma unroll
        for (int k = 0; k < 32; k++) {
            float4 a0 = *(const float4*)&Xb[k*68 + ty*8];
            float4 a1 = *(const float4*)&Xb[k*68 + ty*8 + 4];
            float4 bv = *(const float4*)&Wb[k*132 + tx*4];
            float aa[8] = {a0.x,a0.y,a0.z,a0.w,a1.x,a1.y,a1.z,a1.w};
            float bb[4] = {bv.x,bv.y,bv.z,bv.w};
            #pragma unroll
            for (int i = 0; i < 8; i++)
                #pragma unroll
                for (int j = 0; j < 4; j++)
                    acc[i][j] = fmaf(aa[i], bb[j], acc[i][j]);
        }
        if (kb < 3) {
            __syncthreads();
            int nb = buf ^ 1;
            float* xd = Xs + nb*(32*68) + xr;
            FUSE_XLOAD(xd, (kb+1)*32);
            float* wd = Ws + nb*(32*132) + wk*132 + wc;
            const float* wn = wg + (size_t)(kb+1)*32*Cc;
            *(float4*)(wd  ) = *(const float4*)(wn  );
            *(float4*)(wd+4) = *(const float4*)(wn+4);
            *(float4*)(wd+8) = *(const float4*)(wn+8);
            *(float4*)(wd+12)= *(const float4*)(wn+12);
            __syncthreads();
        }
    }
    #pragma unroll
    for (int i = 0; i < 8; i++) {
        int r = row0 + ty*8 + i;
        float o[4];
        #pragma unroll
        for (int j = 0; j < 4; j++) o[j] = acc[i][j] + bias[tx*4 + j];
        *(float4*)&d_yfin[(size_t)r*Cc + tx*4] = make_float4(o[0],o[1],o[2],o[3]);
    }
}

// ==================== reprojection + residual ====================
__global__ void k_reproj(const float* __restrict__ x, float* __restrict__ out)
{
    __shared__ float yf[16*64];
    int blk = blockIdx.x, b = blockIdx.y, ch = blockIdx.z, t = threadIdx.x;
    int c0 = ch*64;
    #pragma unroll
    for (int l = 0; l < 4; l++) {
        int idx = t + l*256;
        yf[idx] = d_yfin[((size_t)b*1024 + blk*16 + (idx>>6))*Cc + c0 + (idx & 63)];
    }
    __syncthreads();
    float q[16];
    #pragma unroll
    for (int k = 0; k < 16; k++)
        q[k] = d_Q[(((size_t)b*NBLKc + blk)*BNODc + k)*NPc + t];
    int bi = blk >> 3, bj = blk & 7, hi = t >> 4, wi = t & 15;
    size_t base = (size_t)b*Cc*HWc + (size_t)c0*HWc + (size_t)(bi*16+hi)*Wc + (bj*16+wi);
    #pragma unroll 4
    for (int c4 = 0; c4 < 16; c4++) {
        float4 a = make_float4(0.f,0.f,0.f,0.f);
        #pragma unroll
        for (int k = 0; k < 16; k++) {
            float4 yv = *(float4*)&yf[k*64 + c4*4];
            a.x = fmaf(q[k], yv.x, a.x);
            a.y = fmaf(q[k], yv.y, a.y);
            a.z = fmaf(q[k], yv.z, a.z);
            a.w = fmaf(q[k], yv.w, a.w);
        }
        int c = c4*4;
        out[base + (size_t)(c+0)*HWc] = x[base + (size_t)(c+0)*HWc] + a.x;
        out[base + (size_t)(c+1)*HWc] = x[base + (size_t)(c+1)*HWc] + a.y;
        out[base + (size_t)(c+2)*HWc] = x[base + (size_t)(c+2)*HWc] + a.z;
        out[base + (size_t)(c+3)*HWc] = x[base + (size_t)(c+3)*HWc] + a.w;
    }
}

extern "C" void kernel_launch(void* const* d_in, const int* in_sizes, int n_in,
                              void* d_out, int out_size)
{
    const float* x        = (const float*)d_in[0];
    const float* anchor   = (const float*)d_in[1];
    const float* sigma    = (const float*)d_in[2];
    const float* W_root   = (const float*)d_in[3];
    const float* W_nbr    = (const float*)d_in[4];
    const float* wg_src   = (const float*)d_in[5];
    const float* wg_dst   = (const float*)d_in[6];
    const float* b_gate   = (const float*)d_in[7];
    const float* bn_gamma = (const float*)d_in[8];
    const float* bn_beta  = (const float*)d_in[9];
    const float* att_W    = (const float*)d_in[10];
    const float* att_b    = (const float*)d_in[11];
    const float* mlp_W1   = (const float*)d_in[12];
    const float* mlp_b1   = (const float*)d_in[13];
    const float* mlp_W2   = (const float*)d_in[14];
    const float* mlp_b2   = (const float*)d_in[15];
    const float* lineA_w  = (const float*)d_in[16];
    const float* lineA_b  = (const float*)d_in[17];
    const float* lineFu_W = (const float*)d_in[18];
    const float* lineFu_b = (const float*)d_in[19];
    float* out = (float*)d_out;

    cudaFuncSetAttribute(k_proj,     cudaFuncAttributeMaxDynamicSharedMemorySize, PROJ_SMEM);
    cudaFuncSetAttribute(k_gemm2,    cudaFuncAttributeMaxDynamicSharedMemorySize, G64_SMEM);
    cudaFuncSetAttribute(k_attgemm,  cudaFuncAttributeMaxDynamicSharedMemorySize, ATT_SMEM);
    cudaFuncSetAttribute(k_fusegemm, cudaFuncAttributeMaxDynamicSharedMemorySize, FUSE_SMEM);

    k_proj<<<dim3(NBLKc, Bc), 256, PROJ_SMEM>>>(x, anchor, sigma, wg_src, wg_dst, b_gate);
    k_adj<<<dim3(8, 16, Bc), 256>>>();
    k_gemm2<<<dim3(32, 6), 256, G64_SMEM>>>(W_root, W_nbr);
    k_agg<<<dim3(32, 4, 4), 256>>>();
    k_comb<<<dim3(3, 64), 128>>>();
    k_attgemm<<<96, 256, ATT_SMEM>>>(att_W, att_b, bn_gamma, bn_beta);
    k_mlp<<<6, 128>>>(mlp_W1, mlp_b1, mlp_W2, mlp_b2);
    k_fusegemm<<<32, 256, FUSE_SMEM>>>(lineFu_W, lineFu_b, lineA_w, lineA_b);
    k_reproj<<<dim3(NBLKc, Bc, 2), 256>>>(x, out);
}

// round 15
// speedup vs baseline: 1.0786x; 1.0786x over previous
#include <cuda_runtime.h>
#include <math.h>
#include <stdint.h>

#define Bc 2
#define Cc 128
#define Hc 128
#define Wc 128
#define NBLKc 64
#define BNODc 16
#define Nc 1024
#define NPc 256
#define HWc (Hc*Wc)

#define PROJ_SMEM 176512
#define G64_SMEM  51200
#define ATT_SMEM  52224
#define FUSE_SMEM 52768

// ---------------- scratch ----------------
__device__ float d_Q[Bc*NBLKc*BNODc*NPc];
__device__ float d_feats[Bc*Nc*Cc];
__device__ float d_adjm1[(size_t)Bc*Nc*Nc];   // masked+gated, s=1
__device__ float d_adjm2[(size_t)Bc*Nc*Nc];   // masked+gated, s=2
__device__ float d_diagm[Bc*Nc*16];           // masked+gated diag blocks, s=0
__device__ float d_Xnbr[3*Bc*Nc*Cc];
__device__ float d_Xroot[3*Bc*Nc*Cc];
__device__ float d_egi[3*Bc*Nc];      // exp(-(gi + b_gate[s]))
__device__ float d_egj[3*Bc*Nc];      // exp(-gj)
__device__ float d_convp[(size_t)4*4*Nc*Cc];  // [pair(s-1,b)][kc 0..3][n][c]
__device__ float d_conv[3*Bc*Nc*Cc];
__device__ float d_psum[3*64*Cc];
__device__ float d_psq[3*64*Cc];
__device__ float d_y[3*Bc*Nc*Cc];
__device__ float d_poolp[3*2*16*Cc];
__device__ float d_pools2[3*Bc*Cc];
__device__ float d_yfin[Bc*Nc*Cc];

__device__ __forceinline__ float sigf(float z) { return 1.f/(1.f + __expf(-z)); }

__device__ __forceinline__ uint32_t f2tf32(float v) {
    uint32_t r;
    asm("cvt.rna.tf32.f32 %0, %1;" : "=r"(r) : "f"(v));
    return r;
}
__device__ __forceinline__ void mma_tf32(float* c, const uint32_t* a, const uint32_t* b) {
    asm volatile(
        "mma.sync.aligned.m16n8k8.row.col.f32.tf32.tf32.f32 "
        "{%0,%1,%2,%3}, {%4,%5,%6,%7}, {%8,%9}, {%0,%1,%2,%3};\n"
        : "+f"(c[0]), "+f"(c[1]), "+f"(c[2]), "+f"(c[3])
        : "r"(a[0]), "r"(a[1]), "r"(a[2]), "r"(a[3]), "r"(b[0]), "r"(b[1]));
}

// ==================== projection + fused norm/gates (exp form) ====================
__global__ void k_proj(const float* __restrict__ x, const float* __restrict__ anchor,
                       const float* __restrict__ sigma,
                       const float* __restrict__ wsrc, const float* __restrict__ wdst,
                       const float* __restrict__ bgate)
{
    extern __shared__ float sm[];
    float* pix = sm;                                   // [256][129]
    float* sas = sm + 256*129;                         // [16][257]
    float2* ci = (float2*)(sm + 256*129 + 16*257);     // [16][128]: (isig, anc*isig)
    float* Ss  = (float*)(ci + 16*128);                // [16]
    float* vals = Ss + 16;                             // [16][132]
    float* wsd  = vals + 16*132;                       // [6][128]
    int blk = blockIdx.x, b = blockIdx.y;
    int t = threadIdx.x;
    int bi = blk >> 3, bj = blk & 7;
    int hi = t >> 4, wi = t & 15;

    const float* xb = x + (size_t)b*Cc*HWc + (size_t)(bi*16+hi)*Wc + (bj*16+wi);
    #pragma unroll 8
    for (int c = 0; c < Cc; c++) pix[t*129 + c] = xb[(size_t)c*HWc];

    for (int idx = t; idx < BNODc*Cc; idx += 256) {
        float sr = sigma[blk*BNODc*Cc + idx];
        float isg = 1.f + __expf(-sr);                 // 1/sigmoid(sr)
        float an = anchor[blk*BNODc*Cc + idx];
        ci[idx] = make_float2(isg, an*isg);
    }
    for (int i = t; i < 768; i += 256) wsd[i] = (i < 384) ? wsrc[i] : wdst[i-384];
    __syncthreads();

    float lg[16];
    #pragma unroll
    for (int k = 0; k < 16; k++) lg[k] = 0.f;
    for (int c0 = 0; c0 < Cc; c0 += 16) {
        float px[16];
        #pragma unroll
        for (int cc = 0; cc < 16; cc++) px[cc] = pix[t*129 + c0 + cc];
        #pragma unroll
        for (int k = 0; k < 16; k++) {
            float acc = 0.f;
            #pragma unroll
            for (int cc = 0; cc < 16; cc++) {
                float2 v = ci[k*Cc + c0 + cc];
                float d = fmaf(px[cc], v.x, -v.y);
                acc = fmaf(d, d, acc);
            }
            lg[k] += acc;
        }
    }
    float m = -0.5f*lg[0];
    #pragma unroll
    for (int k = 1; k < 16; k++) m = fmaxf(m, -0.5f*lg[k]);
    float sum = 0.f; float e[16];
    #pragma unroll
    for (int k = 0; k < 16; k++) { e[k] = __expf(-0.5f*lg[k] - m); sum += e[k]; }
    float inv = 1.f/sum;
    #pragma unroll
    for (int k = 0; k < 16; k++) {
        float sv = e[k]*inv;
        sas[k*257 + t] = sv;
        d_Q[(((size_t)b*NBLKc + blk)*BNODc + k)*NPc + t] = sv;
    }
    __syncthreads();

    if (t < 16) {
        float s_ = 0.f;
        for (int p = 0; p < 256; p++) s_ += sas[t*257 + p];
        Ss[t] = s_;
    }
    __syncthreads();

    int c = t & 127, kh = t >> 7;
    #pragma unroll
    for (int kk = 0; kk < 8; kk++) {
        int k = kk*2 + kh;
        float acc = 0.f;
        for (int p = 0; p < 256; p++)
            acc = fmaf(sas[k*257 + p], pix[p*129 + c], acc);
        float2 v = ci[k*Cc + c];
        float S = Ss[k];
        vals[k*132 + c] = (v.x*acc - v.y*S) / (S + 1e-9f);
    }
    __syncthreads();

    int wid = t >> 5, lane = t & 31;
    #pragma unroll
    for (int rr = 0; rr < 2; rr++) {
        int k = wid*2 + rr;
        float r[7] = {0.f,0.f,0.f,0.f,0.f,0.f,0.f};
        #pragma unroll
        for (int q = 0; q < 4; q++) {
            int c2 = lane + q*32;
            float v = vals[k*132 + c2];
            r[0] = fmaf(v, v, r[0]);
            #pragma unroll
            for (int s = 0; s < 3; s++) {
                r[1+s] = fmaf(v, wsd[s*128 + c2], r[1+s]);
                r[4+s] = fmaf(v, wsd[(3+s)*128 + c2], r[4+s]);
            }
        }
        #pragma unroll
        for (int o = 16; o; o >>= 1)
            #pragma unroll
            for (int q = 0; q < 7; q++) r[q] += __shfl_xor_sync(0xffffffffu, r[q], o);
        float ninv = 1.f/fmaxf(sqrtf(r[0]), 1e-12f);
        int grow = b*1024 + blk*16 + k;
        #pragma unroll
        for (int q = 0; q < 4; q++) {
            int c2 = lane + q*32;
            d_feats[(size_t)grow*Cc + c2] = vals[k*132 + c2]*ninv;
        }
        if (lane < 3)
            d_egi[lane*2048 + grow] = __expf(-(r[1+lane]*ninv + bgate[lane]));
        else if (lane >= 4 && lane < 7)
            d_egj[(lane-4)*2048 + grow] = __expf(-r[lane]*ninv);
    }
}

// ==================== adj: tf32 mma GEMM + fused mask/gate emit ====================
// C[64,128] = feats_i[64,128] @ feats_j[128,128]^T; grid (8 jt, 16 it, 2 b)
__global__ void __launch_bounds__(256) k_adj()
{
    __shared__ float As[64*36];     // [m][k]
    __shared__ float Bs[128*36];    // [n][k] (feats rows, direct copy)
    __shared__ float egi0s[64], egi1s[64], egi2s[64];
    __shared__ float egj0s[128], egj1s[128], egj2s[128];
    int t = threadIdx.x;
    int jt = blockIdx.x, it = blockIdx.y, b = blockIdx.z;
    const float* fb = d_feats + (size_t)b*Nc*Cc;
    if (t < 64) {
        egi0s[t] = d_egi[       b*1024 + it*64 + t];
        egi1s[t] = d_egi[2048 + b*1024 + it*64 + t];
        egi2s[t] = d_egi[4096 + b*1024 + it*64 + t];
    } else if (t < 192) {
        int j = t - 64;
        egj0s[j] = d_egj[       b*1024 + jt*128 + j];
        egj1s[j] = d_egj[2048 + b*1024 + jt*128 + j];
        egj2s[j] = d_egj[4096 + b*1024 + jt*128 + j];
    }
    int warp = t >> 5, lane = t & 31;
    int wm = (warp >> 2)*32, wn = (warp & 3)*32;
    int lr = lane >> 2, lc = lane & 3;
    float acc[2][4][4];
    #pragma unroll
    for (int mi = 0; mi < 2; mi++)
        #pragma unroll
        for (int ni = 0; ni < 4; ni++)
            #pragma unroll
            for (int q = 0; q < 4; q++) acc[mi][ni][q] = 0.f;

    int am = t >> 2, ak0 = (t & 3)*8;
    int bn = t >> 1, bk0 = (t & 1)*16;

    for (int ks = 0; ks < 128; ks += 32) {
        __syncthreads();
        {   // A [64][32]
            const float* src = fb + (size_t)(it*64 + am)*Cc + ks + ak0;
            float4 v0 = *(const float4*)src, v1 = *(const float4*)(src + 4);
            float* dst = As + am*36 + ak0;
            dst[0] = __uint_as_float(f2tf32(v0.x)); dst[1] = __uint_as_float(f2tf32(v0.y));
            dst[2] = __uint_as_float(f2tf32(v0.z)); dst[3] = __uint_as_float(f2tf32(v0.w));
            dst[4] = __uint_as_float(f2tf32(v1.x)); dst[5] = __uint_as_float(f2tf32(v1.y));
            dst[6] = __uint_as_float(f2tf32(v1.z)); dst[7] = __uint_as_float(f2tf32(v1.w));
        }
        {   // B [128][32] direct rows
            const float* src = fb + (size_t)(jt*128 + bn)*Cc + ks + bk0;
            float* dst = Bs + bn*36 + bk0;
            #pragma unroll
            for (int q = 0; q < 4; q++) {
                float4 v = *(const float4*)(src + q*4);
                dst[q*4+0] = __uint_as_float(f2tf32(v.x));
                dst[q*4+1] = __uint_as_float(f2tf32(v.y));
                dst[q*4+2] = __uint_as_float(f2tf32(v.z));
                dst[q*4+3] = __uint_as_float(f2tf32(v.w));
            }
        }
        __syncthreads();
        #pragma unroll
        for (int k8 = 0; k8 < 32; k8 += 8) {
            uint32_t afr[2][4];
            #pragma unroll
            for (int mi = 0; mi < 2; mi++) {
                int r = wm + mi*16 + lr;
                afr[mi][0] = __float_as_uint(As[(r  )*36 + k8 + lc    ]);
                afr[mi][1] = __float_as_uint(As[(r+8)*36 + k8 + lc    ]);
                afr[mi][2] = __float_as_uint(As[(r  )*36 + k8 + lc + 4]);
                afr[mi][3] = __float_as_uint(As[(r+8)*36 + k8 + lc + 4]);
            }
            uint32_t bfr[4][2];
            #pragma unroll
            for (int ni = 0; ni < 4; ni++) {
                int n = wn + ni*8 + lr;
                bfr[ni][0] = __float_as_uint(Bs[n*36 + k8 + lc    ]);
                bfr[ni][1] = __float_as_uint(Bs[n*36 + k8 + lc + 4]);
            }
            #pragma unroll
            for (int mi = 0; mi < 2; mi++)
                #pragma unroll
                for (int ni = 0; ni < 4; ni++)
                    mma_tf32(acc[mi][ni], afr[mi], bfr[ni]);
        }
    }
    // epilogue: mask + gate emit
    size_t base = (size_t)b*Nc*Nc;
    #pragma unroll
    for (int mi = 0; mi < 2; mi++) {
        #pragma unroll
        for (int ni = 0; ni < 4; ni++) {
            #pragma unroll
            for (int half = 0; half < 2; half++) {
                int li = wm + mi*16 + lr + half*8;
                int gi = it*64 + li;
                int lj = wn + ni*8 + lc*2;
                int gj = jt*128 + lj;
                float a0 = acc[mi][ni][half*2], a1 = acc[mi][ni][half*2+1];
                bool same = (gi >> 4) == (gj >> 4);
                float m1a = (!same && a0 > 0.5f) ? __fdividef(a0, fmaf(egi1s[li], egj1s[lj], 1.f)) : 0.f;
                float m1b = (!same && a1 > 0.5f) ? __fdividef(a1, fmaf(egi1s[li], egj1s[lj+1], 1.f)) : 0.f;
                float m2a = (a0 > 0.3f) ? __fdividef(a0, fmaf(egi2s[li], egj2s[lj], 1.f)) : 0.f;
                float m2b = (a1 > 0.3f) ? __fdividef(a1, fmaf(egi2s[li], egj2s[lj+1], 1.f)) : 0.f;
                size_t ro = base + (size_t)gi*Nc + gj;
                *(float2*)&d_adjm1[ro] = make_float2(m1a, m1b);
                *(float2*)&d_adjm2[ro] = make_float2(m2a, m2b);
                if (same) {
                    float m0a = (a0 > 0.7f) ? __fdividef(a0, fmaf(egi0s[li], egj0s[lj], 1.f)) : 0.f;
                    float m0b = (a1 > 0.7f) ? __fdividef(a1, fmaf(egi0s[li], egj0s[lj+1], 1.f)) : 0.f;
                    *(float2*)&d_diagm[b*16384 + gi*16 + (gj & 15)] = make_float2(m0a, m0b);
                }
            }
        }
    }
}

// ==================== combined root+nbr GEMM (BM=64, dbuf) ====================
__global__ void __launch_bounds__(256) k_gemm2(const float* __restrict__ Wr, const float* __restrict__ Wn)
{
    extern __shared__ float sm[];
    float* Xs = sm;
    float* Ws = sm + 2*32*68;
    int t = threadIdx.x;
    int y = blockIdx.y; int w = (y >= 3); int s = w ? y-3 : y;
    int row0 = blockIdx.x * 64;
    const float* Wp = (w ? Wn : Wr) + s*Cc*Cc;
    float* Yp = (w ? d_Xnbr : d_Xroot) + (size_t)s*2048*Cc;
    int xr = t >> 2, xk = (t & 3)*8;
    int wk = t >> 3, wc = (t & 7)*16;
    const float* xg = d_feats + (size_t)(row0 + xr)*Cc + xk;
    const float* wg = Wp + (size_t)wk*Cc + wc;
    {
        float4 a0 = *(const float4*)xg, a1 = *(const float4*)(xg+4);
        float* xd = Xs + xr;
        xd[(xk+0)*68]=a0.x; xd[(xk+1)*68]=a0.y; xd[(xk+2)*68]=a0.z; xd[(xk+3)*68]=a0.w;
        xd[(xk+4)*68]=a1.x; xd[(xk+5)*68]=a1.y; xd[(xk+6)*68]=a1.z; xd[(xk+7)*68]=a1.w;
        float* wd = Ws + wk*132 + wc;
        *(float4*)(wd  ) = *(const float4*)(wg  );
        *(float4*)(wd+4) = *(const float4*)(wg+4);
        *(float4*)(wd+8) = *(const float4*)(wg+8);
        *(float4*)(wd+12)= *(const float4*)(wg+12);
    }
    __syncthreads();
    int tx = t & 31, ty = t >> 5;
    float acc[8][4] = {};
    #pragma unroll
    for (int kb = 0; kb < 4; kb++) {
        int buf = kb & 1;
        float4 pa0, pa1, pw0, pw1, pw2, pw3;
        if (kb < 3) {
            pa0 = *(const float4*)(xg + (kb+1)*32);
            pa1 = *(const float4*)(xg + (kb+1)*32 + 4);
            const float* wn = wg + (size_t)(kb+1)*32*Cc;
            pw0 = *(const float4*)(wn); pw1 = *(const float4*)(wn+4);
            pw2 = *(const float4*)(wn+8); pw3 = *(const float4*)(wn+12);
        }
        const float* Xb = Xs + buf*(32*68);
        const float* Wb = Ws + buf*(32*132);
        #pragma unroll
        for (int k = 0; k < 32; k++) {
            float4 a0 = *(const float4*)&Xb[k*68 + ty*8];
            float4 a1 = *(const float4*)&Xb[k*68 + ty*8 + 4];
            float4 bv = *(const float4*)&Wb[k*132 + tx*4];
            float aa[8] = {a0.x,a0.y,a0.z,a0.w,a1.x,a1.y,a1.z,a1.w};
            float bb[4] = {bv.x,bv.y,bv.z,bv.w};
            #pragma unroll
            for (int i = 0; i < 8; i++)
                #pragma unroll
                for (int j = 0; j < 4; j++)
                    acc[i][j] = fmaf(aa[i], bb[j], acc[i][j]);
        }
        if (kb < 3) {
            int nb = buf ^ 1;
            float* xd = Xs + nb*(32*68) + xr;
            xd[(xk+0)*68]=pa0.x; xd[(xk+1)*68]=pa0.y; xd[(xk+2)*68]=pa0.z; xd[(xk+3)*68]=pa0.w;
            xd[(xk+4)*68]=pa1.x; xd[(xk+5)*68]=pa1.y; xd[(xk+6)*68]=pa1.z; xd[(xk+7)*68]=pa1.w;
            float* wd = Ws + nb*(32*132) + wk*132 + wc;
            *(float4*)(wd  ) = pw0; *(float4*)(wd+4) = pw1;
            *(float4*)(wd+8) = pw2; *(float4*)(wd+12)= pw3;
            __syncthreads();
        }
    }
    #pragma unroll
    for (int i = 0; i < 8; i++) {
        int r = row0 + ty*8 + i;
        *(float4*)&Yp[(size_t)r*Cc + tx*4]
            = make_float4(acc[i][0],acc[i][1],acc[i][2],acc[i][3]);
    }
}

// ==================== s=1,2 aggregation: tf32 mma (BM=64, R13 geometry) ====================
// C[64,128] += A[64,256] @ B[256,128]; grid (16 m, 4 pair, 4 kc)
__global__ void __launch_bounds__(256) k_agg()
{
    __shared__ float As[64*36];     // [m][k]
    __shared__ float Bs[128*36];    // [n][k]
    int t = threadIdx.x;
    int i0 = blockIdx.x * 64;
    int y = blockIdx.y;
    int s = 1 + (y >> 1), b = y & 1;
    int kc = blockIdx.z;            // 0..3, K=256 chunk
    size_t fb = ((size_t)s*2048 + b*1024)*Cc;
    const float* Asrc = (s == 1 ? d_adjm1 : d_adjm2) + (size_t)b*Nc*Nc;
    int warp = t >> 5, lane = t & 31;
    int wm = (warp >> 2)*32, wn = (warp & 3)*32;
    int lr = lane >> 2, lc = lane & 3;
    float acc[2][4][4];
    #pragma unroll
    for (int mi = 0; mi < 2; mi++)
        #pragma unroll
        for (int ni = 0; ni < 4; ni++)
            #pragma unroll
            for (int q = 0; q < 4; q++) acc[mi][ni][q] = 0.f;

    int am = t >> 2, ak0 = (t & 3)*8;
    int bj = t & 31, bc0 = (t >> 5)*16;

    for (int ks = 0; ks < 256; ks += 32) {
        __syncthreads();
        {
            const float* src = Asrc + (size_t)(i0 + am)*Nc + kc*256 + ks + ak0;
            float4 v0 = *(const float4*)src, v1 = *(const float4*)(src + 4);
            float* dst = As + am*36 + ak0;
            dst[0] = __uint_as_float(f2tf32(v0.x)); dst[1] = __uint_as_float(f2tf32(v0.y));
            dst[2] = __uint_as_float(f2tf32(v0.z)); dst[3] = __uint_as_float(f2tf32(v0.w));
            dst[4] = __uint_as_float(f2tf32(v1.x)); dst[5] = __uint_as_float(f2tf32(v1.y));
            dst[6] = __uint_as_float(f2tf32(v1.z)); dst[7] = __uint_as_float(f2tf32(v1.w));
        }
        {
            const float* src = d_Xnbr + fb + (size_t)(kc*256 + ks + bj)*Cc + bc0;
            #pragma unroll
            for (int q = 0; q < 4; q++) {
                float4 v = *(const float4*)(src + q*4);
                int cb = bc0 + q*4;
                Bs[(cb+0)*36 + bj] = __uint_as_float(f2tf32(v.x));
                Bs[(cb+1)*36 + bj] = __uint_as_float(f2tf32(v.y));
                Bs[(cb+2)*36 + bj] = __uint_as_float(f2tf32(v.z));
                Bs[(cb+3)*36 + bj] = __uint_as_float(f2tf32(v.w));
            }
        }
        __syncthreads();
        #pragma unroll
        for (int k8 = 0; k8 < 32; k8 += 8) {
            uint32_t afr[2][4];
            #pragma unroll
            for (int mi = 0; mi < 2; mi++) {
                int r = wm + mi*16 + lr;
                afr[mi][0] = __float_as_uint(As[(r  )*36 + k8 + lc    ]);
                afr[mi][1] = __float_as_uint(As[(r+8)*36 + k8 + lc    ]);
                afr[mi][2] = __float_as_uint(As[(r  )*36 + k8 + lc + 4]);
                afr[mi][3] = __float_as_uint(As[(r+8)*36 + k8 + lc + 4]);
            }
            uint32_t bfr[4][2];
            #pragma unroll
            for (int ni = 0; ni < 4; ni++) {
                int n = wn + ni*8 + lr;
                bfr[ni][0] = __float_as_uint(Bs[n*36 + k8 + lc    ]);
                bfr[ni][1] = __float_as_uint(Bs[n*36 + k8 + lc + 4]);
            }
            #pragma unroll
            for (int mi = 0; mi < 2; mi++)
                #pragma unroll
                for (int ni = 0; ni < 4; ni++)
                    mma_tf32(acc[mi][ni], afr[mi], bfr[ni]);
        }
    }
    size_t pb = (size_t)y*524288 + (size_t)kc*131072;
    #pragma unroll
    for (int mi = 0; mi < 2; mi++) {
        #pragma unroll
        for (int ni = 0; ni < 4; ni++) {
            int r0 = i0 + wm + mi*16 + lr;
            int col = wn + ni*8 + lc*2;
            *(float2*)&d_convp[pb + (size_t)r0*Cc + col]
                = make_float2(acc[mi][ni][0], acc[mi][ni][1]);
            *(float2*)&d_convp[pb + (size_t)(r0+8)*Cc + col]
                = make_float2(acc[mi][ni][2], acc[mi][ni][3]);
        }
    }
}

// ==================== combine partials + BN partial stats (+ s=0 diag agg) ====================
__global__ void k_comb()
{
    int s = blockIdx.x, part = blockIdx.y, t = threadIdx.x;
    float su = 0.f, sq = 0.f;
    int rbase = part*32;
    if (s == 0) {
        __shared__ float Xn[32][129];
        __shared__ float Am[2][16][17];
        int b = rbase >> 10, n0 = rbase & 1023;
        #pragma unroll
        for (int j2 = 0; j2 < 32; j2++)
            Xn[j2][t] = d_Xnbr[((size_t)b*1024 + n0 + j2)*Cc + t];
        #pragma unroll
        for (int l = 0; l < 4; l++) {
            int id = t + l*128;
            int lb = id >> 8, i = (id >> 4) & 15, j = id & 15;
            Am[lb][i][j] = d_diagm[b*16384 + (n0 + lb*16 + i)*16 + j];
        }
        __syncthreads();
        for (int r0 = 0; r0 < 32; r0++) {
            int rr = rbase + r0;
            int lb = r0 >> 4, i = r0 & 15;
            size_t ci = (size_t)rr*Cc + t;
            float v = d_Xroot[ci];
            #pragma unroll
            for (int j = 0; j < 16; j++)
                v = fmaf(Am[lb][i][j], Xn[lb*16 + j][t], v);
            d_conv[ci] = v;
            su += v; sq = fmaf(v, v, sq);
        }
    } else {
        for (int r0 = 0; r0 < 32; r0++) {
            int rr = rbase + r0;
            size_t ci = ((size_t)s*2048 + rr)*Cc + t;
            int b = rr >> 10, n = rr & 1023;
            size_t pbb = ((size_t)(s-1)*2 + b)*524288 + (size_t)n*Cc + t;
            float v = d_Xroot[ci] + d_convp[pbb] + d_convp[pbb + 131072]
                    + d_convp[pbb + 262144] + d_convp[pbb + 393216];
            d_conv[ci] = v;
            su += v; sq = fmaf(v, v, sq);
        }
    }
    d_psum[(s*64 + part)*Cc + t] = su;
    d_psq [(s*64 + part)*Cc + t] = sq;
}

// ==================== att GEMM ====================
__global__ void __launch_bounds__(256) k_attgemm(const float* __restrict__ attW, const float* __restrict__ attb,
                          const float* __restrict__ gamma, const float* __restrict__ beta)
{
    extern __shared__ float sm[];
    float* Xs = sm;
    float* Ws = sm + 2*32*68;
    float* scl = sm + 12800;
    float* sft = scl + 128;
    int t = threadIdx.x;
    int row0 = blockIdx.x * 64;
    int s = row0 >> 11;
    if (t < 128) {
        float su = 0.f, sq = 0.f;
        #pragma unroll 8
        for (int p = 0; p < 64; p++) {
            su += d_psum[(s*64+p)*Cc + t];
            sq += d_psq [(s*64+p)*Cc + t];
        }
        float mu = su / 2048.f;
        float va = sq / 2048.f - mu*mu;
        float sc = gamma[s*Cc + t]*rsqrtf(va + 1e-5f);
        scl[t] = sc;
        sft[t] = beta[s*Cc + t] - mu*sc;
    }
    __syncthreads();
    const float* Wp = attW + s*Cc*Cc;
    int xr = t >> 2, xk = (t & 3)*8;
    int wk = t >> 3, wc = (t & 7)*16;
    int fr = (row0 + xr) & 2047;
    const float* cg = d_conv + (size_t)(row0 + xr)*Cc + xk;
    const float* fg = d_feats + (size_t)fr*Cc + xk;
    const float* wg = Wp + (size_t)wk*Cc + wc;
    {
        float4 c0 = *(const float4*)cg, c1 = *(const float4*)(cg+4);
        float4 f0 = *(const float4*)fg, f1 = *(const float4*)(fg+4);
        float* xd = Xs + xr;
        xd[(xk+0)*68] = c0.x*scl[xk+0]+sft[xk+0]+f0.x;
        xd[(xk+1)*68] = c0.y*scl[xk+1]+sft[xk+1]+f0.y;
        xd[(xk+2)*68] = c0.z*scl[xk+2]+sft[xk+2]+f0.z;
        xd[(xk+3)*68] = c0.w*scl[xk+3]+sft[xk+3]+f0.w;
        xd[(xk+4)*68] = c1.x*scl[xk+4]+sft[xk+4]+f1.x;
        xd[(xk+5)*68] = c1.y*scl[xk+5]+sft[xk+5]+f1.y;
        xd[(xk+6)*68] = c1.z*scl[xk+6]+sft[xk+6]+f1.z;
        xd[(xk+7)*68] = c1.w*scl[xk+7]+sft[xk+7]+f1.w;
        float* wd = Ws + wk*132 + wc;
        *(float4*)(wd  ) = *(const float4*)(wg  );
        *(float4*)(wd+4) = *(const float4*)(wg+4);
        *(float4*)(wd+8) = *(const float4*)(wg+8);
        *(float4*)(wd+12)= *(const float4*)(wg+12);
    }
    __syncthreads();
    int tx = t & 31, ty = t >> 5;
    float acc[8][4] = {};
    #pragma unroll
    for (int kb = 0; kb < 4; kb++) {
        int buf = kb & 1;
        float4 pc0, pc1, pf0, pf1, pw0, pw1, pw2, pw3;
        if (kb < 3) {
            pc0 = *(const float4*)(cg + (kb+1)*32);
            pc1 = *(const float4*)(cg + (kb+1)*32 + 4);
            pf0 = *(const float4*)(fg + (kb+1)*32);
            pf1 = *(const float4*)(fg + (kb+1)*32 + 4);
            const float* wn = wg + (size_t)(kb+1)*32*Cc;
            pw0 = *(const float4*)(wn); pw1 = *(const float4*)(wn+4);
            pw2 = *(const float4*)(wn+8); pw3 = *(const float4*)(wn+12);
        }
        const float* Xb = Xs + buf*(32*68);
        const float* Wb = Ws + buf*(32*132);
        #pragma unroll
        for (int k = 0; k < 32; k++) {
            float4 a0 = *(const float4*)&Xb[k*68 + ty*8];
            float4 a1 = *(const float4*)&Xb[k*68 + ty*8 + 4];
            float4 bv = *(const float4*)&Wb[k*132 + tx*4];
            float aa[8] = {a0.x,a0.y,a0.z,a0.w,a1.x,a1.y,a1.z,a1.w};
            float bb[4] = {bv.x,bv.y,bv.z,bv.w};
            #pragma unroll
            for (int i = 0; i < 8; i++)
                #pragma unroll
                for (int j = 0; j < 4; j++)
                    acc[i][j] = fmaf(aa[i], bb[j], acc[i][j]);
        }
        if (kb < 3) {
            int nb = buf ^ 1;
            int kbase = (kb+1)*32;
            float* xd = Xs + nb*(32*68) + xr;
            xd[(xk+0)*68] = pc0.x*scl[kbase+xk+0]+sft[kbase+xk+0]+pf0.x;
            xd[(xk+1)*68] = pc0.y*scl[kbase+xk+1]+sft[kbase+xk+1]+pf0.y;
            xd[(xk+2)*68] = pc0.z*scl[kbase+xk+2]+sft[kbase+xk+2]+pf0.z;
            xd[(xk+3)*68] = pc0.w*scl[kbase+xk+3]+sft[kbase+xk+3]+pf0.w;
            xd[(xk+4)*68] = pc1.x*scl[kbase+xk+4]+sft[kbase+xk+4]+pf1.x;
            xd[(xk+5)*68] = pc1.y*scl[kbase+xk+5]+sft[kbase+xk+5]+pf1.y;
            xd[(xk+6)*68] = pc1.z*scl[kbase+xk+6]+sft[kbase+xk+6]+pf1.z;
            xd[(xk+7)*68] = pc1.w*scl[kbase+xk+7]+sft[kbase+xk+7]+pf1.w;
            float* wd = Ws + nb*(32*132) + wk*132 + wc;
            *(float4*)(wd  ) = pw0; *(float4*)(wd+4) = pw1;
            *(float4*)(wd+8) = pw2; *(float4*)(wd+12)= pw3;
            __syncthreads();
        }
    }
    float colmax[4] = {-3.4e38f,-3.4e38f,-3.4e38f,-3.4e38f};
    #pragma unroll
    for (int i = 0; i < 8; i++) {
        int row = row0 + ty*8 + i;
        int frr = row & 2047;
        float4 cv = *(const float4*)&d_conv[(size_t)row*Cc + tx*4];
        float4 fv = *(const float4*)&d_feats[(size_t)frr*Cc + tx*4];
        float cva[4] = {cv.x,cv.y,cv.z,cv.w};
        float fva[4] = {fv.x,fv.y,fv.z,fv.w};
        float o[4];
        #pragma unroll
        for (int j = 0; j < 4; j++) {
            int c = tx*4 + j;
            float v = acc[i][j] + attb[s*Cc + c];
            float hv = cva[j]*scl[c] + sft[c] + fva[j];
            float yv = fmaxf(sigf(v)*hv, 0.f);
            o[j] = yv;
            colmax[j] = fmaxf(colmax[j], yv);
        }
        *(float4*)&d_y[(size_t)row*Cc + tx*4] = make_float4(o[0],o[1],o[2],o[3]);
    }
    __syncthreads();
    float* pm = sm;
    #pragma unroll
    for (int j = 0; j < 4; j++) pm[ty*132 + tx*4 + j] = colmax[j];
    __syncthreads();
    if (t < 128) {
        float m = -3.4e38f;
        #pragma unroll
        for (int q = 0; q < 8; q++) m = fmaxf(m, pm[q*132 + t]);
        int bb = (row0 >> 10) & 1, tl = (row0 & 1023) >> 6;
        d_poolp[((s*2 + bb)*16 + tl)*Cc + t] = m;
    }
}

// ==================== mlp ====================
__global__ void k_mlp(const float* __restrict__ W1, const float* __restrict__ b1,
                      const float* __restrict__ W2, const float* __restrict__ b2)
{
    int sb = blockIdx.x, t = threadIdx.x;
    int s = sb >> 1;
    __shared__ float p[128], t1[128];
    float m = -3.4e38f;
    #pragma unroll
    for (int ch = 0; ch < 16; ch++) m = fmaxf(m, d_poolp[(sb*16 + ch)*Cc + t]);
    p[t] = m;
    __syncthreads();
    float acc = b1[s*Cc + t];
    #pragma unroll 8
    for (int k = 0; k < 128; k++) acc = fmaf(p[k], W1[s*Cc*Cc + k*Cc + t], acc);
    t1[t] = fmaxf(acc, 0.f);
    __syncthreads();
    float acc2 = b2[s*Cc + t];
    #pragma unroll 8
    for (int k = 0; k < 128; k++) acc2 = fmaf(t1[k], W2[s*Cc*Cc + k*Cc + t], acc2);
    d_pools2[sb*Cc + t] = sigf(acc2);
}

// ==================== final GEMM: fused softmax-mix X + Aw prologue ====================
__global__ void __launch_bounds__(256) k_fusegemm(const float* __restrict__ W, const float* __restrict__ bias,
                           const float* __restrict__ lw, const float* __restrict__ lb)
{
    extern __shared__ float sm[];
    float* Xs = sm;
    float* Ws = sm + 2*32*68;
    float* p2s = sm + 12800;
    float* aw  = p2s + 384;
    int t = threadIdx.x;
    int row0 = blockIdx.x * 64;
    int b = row0 >> 10;
    for (int i = t; i < 384; i += 256)
        p2s[i] = d_pools2[((i >> 7)*2 + b)*Cc + (i & 127)];
    __syncthreads();
    if (t < 32) {
        float av[3];
        #pragma unroll
        for (int s = 0; s < 3; s++) {
            float r = 0.f;
            #pragma unroll
            for (int q = 0; q < 4; q++) {
                int c = t + q*32;
                r = fmaf(p2s[s*128 + c], lw[s*Cc + c], r);
            }
            #pragma unroll
            for (int o = 16; o; o >>= 1) r += __shfl_xor_sync(0xffffffffu, r, o);
            av[s] = r + lb[s];
        }
        if (t == 0) {
            float m = fmaxf(av[0], fmaxf(av[1], av[2]));
            float e0 = __expf(av[0]-m), e1 = __expf(av[1]-m), e2 = __expf(av[2]-m);
            float inv = 1.f/(e0+e1+e2);
            aw[0] = e0*inv; aw[1] = e1*inv; aw[2] = e2*inv;
        }
    }
    __syncthreads();
    float aw0 = aw[0], aw1 = aw[1], aw2 = aw[2];
    int xr = t >> 2, xk = (t & 3)*8;
    int wk = t >> 3, wc = (t & 7)*16;
    const float* y0 = d_y + (size_t)(row0 + xr)*Cc + xk;
    const float* y1 = y0 + (size_t)2048*Cc;
    const float* y2 = y1 + (size_t)2048*Cc;
    const float* wg = W + (size_t)wk*Cc + wc;
    #define FUSE_XLOAD(dst, off) { \
        float4 v0 = *(const float4*)(y0+(off)), v0b = *(const float4*)(y0+(off)+4); \
        float4 v1 = *(const float4*)(y1+(off)), v1b = *(const float4*)(y1+(off)+4); \
        float4 v2 = *(const float4*)(y2+(off)), v2b = *(const float4*)(y2+(off)+4); \
        int kb0 = (off) + xk; \
        dst[(xk+0)*68] = aw0*p2s[kb0+0]*v0.x + aw1*p2s[128+kb0+0]*v1.x + aw2*p2s[256+kb0+0]*v2.x; \
        dst[(xk+1)*68] = aw0*p2s[kb0+1]*v0.y + aw1*p2s[128+kb0+1]*v1.y + aw2*p2s[256+kb0+1]*v2.y; \
        dst[(xk+2)*68] = aw0*p2s[kb0+2]*v0.z + aw1*p2s[128+kb0+2]*v1.z + aw2*p2s[256+kb0+2]*v2.z; \
        dst[(xk+3)*68] = aw0*p2s[kb0+3]*v0.w + aw1*p2s[128+kb0+3]*v1.w + aw2*p2s[256+kb0+3]*v2.w; \
        dst[(xk+4)*68] = aw0*p2s[kb0+4]*v0b.x + aw1*p2s[128+kb0+4]*v1b.x + aw2*p2s[256+kb0+4]*v2b.x; \
        dst[(xk+5)*68] = aw0*p2s[kb0+5]*v0b.y + aw1*p2s[128+kb0+5]*v1b.y + aw2*p2s[256+kb0+5]*v2b.y; \
        dst[(xk+6)*68] = aw0*p2s[kb0+6]*v0b.z + aw1*p2s[128+kb0+6]*v1b.z + aw2*p2s[256+kb0+6]*v2b.z; \
        dst[(xk+7)*68] = aw0*p2s[kb0+7]*v0b.w + aw1*p2s[128+kb0+7]*v1b.w + aw2*p2s[256+kb0+7]*v2b.w; \
    }
    {
        float* xd = Xs + xr;
        FUSE_XLOAD(xd, 0);
        float* wd = Ws + wk*132 + wc;
        *(float4*)(wd  ) = *(const float4*)(wg  );
        *(float4*)(wd+4) = *(const float4*)(wg+4);
        *(float4*)(wd+8) = *(const float4*)(wg+8);
        *(float4*)(wd+12)= *(const float4*)(wg+12);
    }
    __syncthreads();
    int tx = t & 31, ty = t >> 5;
    float acc[8][4] = {};
    #pragma unroll
    for (int kb = 0; kb < 4; kb++) {
        int buf = kb & 1;
        const float* Xb = Xs + buf*(32*68);
        const float* Wb = Ws + buf*(32*132);
        #pragma unroll
        for (int k = 0; k < 32; k++) {
            float4 a0 = *(const float4*)&Xb[k*68 + ty*8];
            float4 a1 = *(const float4*)&Xb[k*68 + ty*8 + 4];
            float4 bv = *(const float4*)&Wb[k*132 + tx*4];
            float aa[8] = {a0.x,a0.y,a0.z,a0.w,a1.x,a1.y,a1.z,a1.w};
            float bb[4] = {bv.x,bv.y,bv.z,bv.w};
            #pragma unroll
            for (int i = 0; i < 8; i++)
                #pragma unroll
                for (int j = 0; j < 4; j++)
                    acc[i][j] = fmaf(aa[i], bb[j], acc[i][j]);
        }
        if (kb < 3) {
            __syncthreads();
            int nb = buf ^ 1;
            float* xd = Xs + nb*(32*68) + xr;
            FUSE_XLOAD(xd, (kb+1)*32);
            float* wd = Ws + nb*(32*132) + wk*132 + wc;
            const float* wn = wg + (size_t)(kb+1)*32*Cc;
            *(float4*)(wd  ) = *(const float4*)(wn  );
            *(float4*)(wd+4) = *(const float4*)(wn+4);
            *(float4*)(wd+8) = *(const float4*)(wn+8);
            *(float4*)(wd+12)= *(const float4*)(wn+12);
            __syncthreads();
        }
    }
    #pragma unroll
    for (int i = 0; i < 8; i++) {
        int r = row0 + ty*8 + i;
        float o[4];
        #pragma unroll
        for (int j = 0; j < 4; j++) o[j] = acc[i][j] + bias[tx*4 + j];
        *(float4*)&d_yfin[(size_t)r*Cc + tx*4] = make_float4(o[0],o[1],o[2],o[3]);
    }
}

// ==================== reprojection + residual ====================
__global__ void k_reproj(const float* __restrict__ x, float* __restrict__ out)
{
    __shared__ float yf[16*64];
    int blk = blockIdx.x, b = blockIdx.y, ch = blockIdx.z, t = threadIdx.x;
    int c0 = ch*64;
    #pragma unroll
    for (int l = 0; l < 4; l++) {
        int idx = t + l*256;
        yf[idx] = d_yfin[((size_t)b*1024 + blk*16 + (idx>>6))*Cc + c0 + (idx & 63)];
    }
    __syncthreads();
    float q[16];
    #pragma unroll
    for (int k = 0; k < 16; k++)
        q[k] = d_Q[(((size_t)b*NBLKc + blk)*BNODc + k)*NPc + t];
    int bi = blk >> 3, bj = blk & 7, hi = t >> 4, wi = t & 15;
    size_t base = (size_t)b*Cc*HWc + (size_t)c0*HWc + (size_t)(bi*16+hi)*Wc + (bj*16+wi);
    #pragma unroll 4
    for (int c4 = 0; c4 < 16; c4++) {
        float4 a = make_float4(0.f,0.f,0.f,0.f);
        #pragma unroll
        for (int k = 0; k < 16; k++) {
            float4 yv = *(float4*)&yf[k*64 + c4*4];
            a.x = fmaf(q[k], yv.x, a.x);
            a.y = fmaf(q[k], yv.y, a.y);
            a.z = fmaf(q[k], yv.z, a.z);
            a.w = fmaf(q[k], yv.w, a.w);
        }
        int c = c4*4;
        out[base + (size_t)(c+0)*HWc] = x[base + (size_t)(c+0)*HWc] + a.x;
        out[base + (size_t)(c+1)*HWc] = x[base + (size_t)(c+1)*HWc] + a.y;
        out[base + (size_t)(c+2)*HWc] = x[base + (size_t)(c+2)*HWc] + a.z;
        out[base + (size_t)(c+3)*HWc] = x[base + (size_t)(c+3)*HWc] + a.w;
    }
}

extern "C" void kernel_launch(void* const* d_in, const int* in_sizes, int n_in,
                              void* d_out, int out_size)
{
    const float* x        = (const float*)d_in[0];
    const float* anchor   = (const float*)d_in[1];
    const float* sigma    = (const float*)d_in[2];
    const float* W_root   = (const float*)d_in[3];
    const float* W_nbr    = (const float*)d_in[4];
    const float* wg_src   = (const float*)d_in[5];
    const float* wg_dst   = (const float*)d_in[6];
    const float* b_gate   = (const float*)d_in[7];
    const float* bn_gamma = (const float*)d_in[8];
    const float* bn_beta  = (const float*)d_in[9];
    const float* att_W    = (const float*)d_in[10];
    const float* att_b    = (const float*)d_in[11];
    const float* mlp_W1   = (const float*)d_in[12];
    const float* mlp_b1   = (const float*)d_in[13];
    const float* mlp_W2   = (const float*)d_in[14];
    const float* mlp_b2   = (const float*)d_in[15];
    const float* lineA_w  = (const float*)d_in[16];
    const float* lineA_b  = (const float*)d_in[17];
    const float* lineFu_W = (const float*)d_in[18];
    const float* lineFu_b = (const float*)d_in[19];
    float* out = (float*)d_out;

    cudaFuncSetAttribute(k_proj,     cudaFuncAttributeMaxDynamicSharedMemorySize, PROJ_SMEM);
    cudaFuncSetAttribute(k_gemm2,    cudaFuncAttributeMaxDynamicSharedMemorySize, G64_SMEM);
    cudaFuncSetAttribute(k_attgemm,  cudaFuncAttributeMaxDynamicSharedMemorySize, ATT_SMEM);
    cudaFuncSetAttribute(k_fusegemm, cudaFuncAttributeMaxDynamicSharedMemorySize, FUSE_SMEM);

    k_proj<<<dim3(NBLKc, Bc), 256, PROJ_SMEM>>>(x, anchor, sigma, wg_src, wg_dst, b_gate);
    k_adj<<<dim3(8, 16, Bc), 256>>>();
    k_gemm2<<<dim3(32, 6), 256, G64_SMEM>>>(W_root, W_nbr);
    k_agg<<<dim3(16, 4, 4), 256>>>();
    k_comb<<<dim3(3, 64), 128>>>();
    k_attgemm<<<96, 256, ATT_SMEM>>>(att_W, att_b, bn_gamma, bn_beta);
    k_mlp<<<6, 128>>>(mlp_W1, mlp_b1, mlp_W2, mlp_b2);
    k_fusegemm<<<32, 256, FUSE_SMEM>>>(lineFu_W, lineFu_b, lineA_w, lineA_b);
    k_reproj<<<dim3(NBLKc, Bc, 2), 256>>>(x, out);
}

// round 16
// speedup vs baseline: 1.1034x; 1.0230x over previous
#include <cuda_runtime.h>
#include <math.h>
#include <stdint.h>

#define Bc 2
#define Cc 128
#define Hc 128
#define Wc 128
#define NBLKc 64
#define BNODc 16
#define Nc 1024
#define NPc 256
#define HWc (Hc*Wc)

#define PROJ_SMEM 176512
#define G64_SMEM  51200
#define ATT_SMEM  52224
#define FUSE_SMEM 52768

// ---------------- scratch ----------------
__device__ float d_Q[Bc*NBLKc*BNODc*NPc];
__device__ float d_feats[Bc*Nc*Cc];
__device__ float d_adjm1[(size_t)Bc*Nc*Nc];   // masked+gated, s=1
__device__ float d_adjm2[(size_t)Bc*Nc*Nc];   // masked+gated, s=2
__device__ float d_diagm[Bc*Nc*16];           // masked+gated diag blocks, s=0
__device__ float d_Xnbr[3*Bc*Nc*Cc];
__device__ float d_Xroot[3*Bc*Nc*Cc];
__device__ float d_egi[3*Bc*Nc];      // exp(-(gi + b_gate[s]))
__device__ float d_egj[3*Bc*Nc];      // exp(-gj)
__device__ float d_convp[(size_t)4*8*Nc*Cc];  // [pair(s-1,b)][kc 0..7][n][c]
__device__ float d_conv[3*Bc*Nc*Cc];
__device__ float d_psum[3*128*Cc];
__device__ float d_psq[3*128*Cc];
__device__ float d_y[3*Bc*Nc*Cc];
__device__ float d_poolp[3*2*16*Cc];
__device__ float d_pools2[3*Bc*Cc];
__device__ float d_yfin[Bc*Nc*Cc];

__device__ __forceinline__ float sigf(float z) { return 1.f/(1.f + __expf(-z)); }

__device__ __forceinline__ uint32_t f2tf32(float v) {
    uint32_t r;
    asm("cvt.rna.tf32.f32 %0, %1;" : "=r"(r) : "f"(v));
    return r;
}
__device__ __forceinline__ void mma_tf32(float* c, const uint32_t* a, const uint32_t* b) {
    asm volatile(
        "mma.sync.aligned.m16n8k8.row.col.f32.tf32.tf32.f32 "
        "{%0,%1,%2,%3}, {%4,%5,%6,%7}, {%8,%9}, {%0,%1,%2,%3};\n"
        : "+f"(c[0]), "+f"(c[1]), "+f"(c[2]), "+f"(c[3])
        : "r"(a[0]), "r"(a[1]), "r"(a[2]), "r"(a[3]), "r"(b[0]), "r"(b[1]));
}

// ==================== projection + fused norm/gates (exp form) ====================
__global__ void k_proj(const float* __restrict__ x, const float* __restrict__ anchor,
                       const float* __restrict__ sigma,
                       const float* __restrict__ wsrc, const float* __restrict__ wdst,
                       const float* __restrict__ bgate)
{
    extern __shared__ float sm[];
    float* pix = sm;                                   // [256][129]
    float* sas = sm + 256*129;                         // [16][257]
    float2* ci = (float2*)(sm + 256*129 + 16*257);     // [16][128]: (isig, anc*isig)
    float* Ss  = (float*)(ci + 16*128);                // [16]
    float* vals = Ss + 16;                             // [16][132]
    float* wsd  = vals + 16*132;                       // [6][128]
    int blk = blockIdx.x, b = blockIdx.y;
    int t = threadIdx.x;
    int bi = blk >> 3, bj = blk & 7;
    int hi = t >> 4, wi = t & 15;

    const float* xb = x + (size_t)b*Cc*HWc + (size_t)(bi*16+hi)*Wc + (bj*16+wi);
    #pragma unroll 8
    for (int c = 0; c < Cc; c++) pix[t*129 + c] = xb[(size_t)c*HWc];

    for (int idx = t; idx < BNODc*Cc; idx += 256) {
        float sr = sigma[blk*BNODc*Cc + idx];
        float isg = 1.f + __expf(-sr);                 // 1/sigmoid(sr)
        float an = anchor[blk*BNODc*Cc + idx];
        ci[idx] = make_float2(isg, an*isg);
    }
    for (int i = t; i < 768; i += 256) wsd[i] = (i < 384) ? wsrc[i] : wdst[i-384];
    __syncthreads();

    float lg[16];
    #pragma unroll
    for (int k = 0; k < 16; k++) lg[k] = 0.f;
    for (int c0 = 0; c0 < Cc; c0 += 16) {
        float px[16];
        #pragma unroll
        for (int cc = 0; cc < 16; cc++) px[cc] = pix[t*129 + c0 + cc];
        #pragma unroll
        for (int k = 0; k < 16; k++) {
            float acc = 0.f;
            #pragma unroll
            for (int cc = 0; cc < 16; cc++) {
                float2 v = ci[k*Cc + c0 + cc];
                float d = fmaf(px[cc], v.x, -v.y);
                acc = fmaf(d, d, acc);
            }
            lg[k] += acc;
        }
    }
    float m = -0.5f*lg[0];
    #pragma unroll
    for (int k = 1; k < 16; k++) m = fmaxf(m, -0.5f*lg[k]);
    float sum = 0.f; float e[16];
    #pragma unroll
    for (int k = 0; k < 16; k++) { e[k] = __expf(-0.5f*lg[k] - m); sum += e[k]; }
    float inv = 1.f/sum;
    #pragma unroll
    for (int k = 0; k < 16; k++) {
        float sv = e[k]*inv;
        sas[k*257 + t] = sv;
        d_Q[(((size_t)b*NBLKc + blk)*BNODc + k)*NPc + t] = sv;
    }
    __syncthreads();

    if (t < 16) {
        float s_ = 0.f;
        for (int p = 0; p < 256; p++) s_ += sas[t*257 + p];
        Ss[t] = s_;
    }
    __syncthreads();

    int c = t & 127, kh = t >> 7;
    #pragma unroll
    for (int kk = 0; kk < 8; kk++) {
        int k = kk*2 + kh;
        float acc = 0.f;
        for (int p = 0; p < 256; p++)
            acc = fmaf(sas[k*257 + p], pix[p*129 + c], acc);
        float2 v = ci[k*Cc + c];
        float S = Ss[k];
        vals[k*132 + c] = (v.x*acc - v.y*S) / (S + 1e-9f);
    }
    __syncthreads();

    int wid = t >> 5, lane = t & 31;
    #pragma unroll
    for (int rr = 0; rr < 2; rr++) {
        int k = wid*2 + rr;
        float r[7] = {0.f,0.f,0.f,0.f,0.f,0.f,0.f};
        #pragma unroll
        for (int q = 0; q < 4; q++) {
            int c2 = lane + q*32;
            float v = vals[k*132 + c2];
            r[0] = fmaf(v, v, r[0]);
            #pragma unroll
            for (int s = 0; s < 3; s++) {
                r[1+s] = fmaf(v, wsd[s*128 + c2], r[1+s]);
                r[4+s] = fmaf(v, wsd[(3+s)*128 + c2], r[4+s]);
            }
        }
        #pragma unroll
        for (int o = 16; o; o >>= 1)
            #pragma unroll
            for (int q = 0; q < 7; q++) r[q] += __shfl_xor_sync(0xffffffffu, r[q], o);
        float ninv = 1.f/fmaxf(sqrtf(r[0]), 1e-12f);
        int grow = b*1024 + blk*16 + k;
        #pragma unroll
        for (int q = 0; q < 4; q++) {
            int c2 = lane + q*32;
            d_feats[(size_t)grow*Cc + c2] = vals[k*132 + c2]*ninv;
        }
        if (lane < 3)
            d_egi[lane*2048 + grow] = __expf(-(r[1+lane]*ninv + bgate[lane]));
        else if (lane >= 4 && lane < 7)
            d_egj[(lane-4)*2048 + grow] = __expf(-r[lane]*ninv);
    }
}

// ==================== adj: tf32 mma GEMM + fused mask/gate emit ====================
// C[64,128] = feats_i[64,128] @ feats_j[128,128]^T; grid (8 jt, 16 it, 2 b)
__global__ void __launch_bounds__(256) k_adj()
{
    __shared__ float As[64*36];     // [m][k]
    __shared__ float Bs[128*36];    // [n][k] (feats rows, direct copy)
    __shared__ float egi0s[64], egi1s[64], egi2s[64];
    __shared__ float egj0s[128], egj1s[128], egj2s[128];
    int t = threadIdx.x;
    int jt = blockIdx.x, it = blockIdx.y, b = blockIdx.z;
    const float* fb = d_feats + (size_t)b*Nc*Cc;
    if (t < 64) {
        egi0s[t] = d_egi[       b*1024 + it*64 + t];
        egi1s[t] = d_egi[2048 + b*1024 + it*64 + t];
        egi2s[t] = d_egi[4096 + b*1024 + it*64 + t];
    } else if (t < 192) {
        int j = t - 64;
        egj0s[j] = d_egj[       b*1024 + jt*128 + j];
        egj1s[j] = d_egj[2048 + b*1024 + jt*128 + j];
        egj2s[j] = d_egj[4096 + b*1024 + jt*128 + j];
    }
    int warp = t >> 5, lane = t & 31;
    int wm = (warp >> 2)*32, wn = (warp & 3)*32;
    int lr = lane >> 2, lc = lane & 3;
    float acc[2][4][4];
    #pragma unroll
    for (int mi = 0; mi < 2; mi++)
        #pragma unroll
        for (int ni = 0; ni < 4; ni++)
            #pragma unroll
            for (int q = 0; q < 4; q++) acc[mi][ni][q] = 0.f;

    int am = t >> 2, ak0 = (t & 3)*8;
    int bn = t >> 1, bk0 = (t & 1)*16;

    for (int ks = 0; ks < 128; ks += 32) {
        __syncthreads();
        {   // A [64][32]
            const float* src = fb + (size_t)(it*64 + am)*Cc + ks + ak0;
            float4 v0 = *(const float4*)src, v1 = *(const float4*)(src + 4);
            float* dst = As + am*36 + ak0;
            dst[0] = __uint_as_float(f2tf32(v0.x)); dst[1] = __uint_as_float(f2tf32(v0.y));
            dst[2] = __uint_as_float(f2tf32(v0.z)); dst[3] = __uint_as_float(f2tf32(v0.w));
            dst[4] = __uint_as_float(f2tf32(v1.x)); dst[5] = __uint_as_float(f2tf32(v1.y));
            dst[6] = __uint_as_float(f2tf32(v1.z)); dst[7] = __uint_as_float(f2tf32(v1.w));
        }
        {   // B [128][32] direct rows
            const float* src = fb + (size_t)(jt*128 + bn)*Cc + ks + bk0;
            float* dst = Bs + bn*36 + bk0;
            #pragma unroll
            for (int q = 0; q < 4; q++) {
                float4 v = *(const float4*)(src + q*4);
                dst[q*4+0] = __uint_as_float(f2tf32(v.x));
                dst[q*4+1] = __uint_as_float(f2tf32(v.y));
                dst[q*4+2] = __uint_as_float(f2tf32(v.z));
                dst[q*4+3] = __uint_as_float(f2tf32(v.w));
            }
        }
        __syncthreads();
        #pragma unroll
        for (int k8 = 0; k8 < 32; k8 += 8) {
            uint32_t afr[2][4];
            #pragma unroll
            for (int mi = 0; mi < 2; mi++) {
                int r = wm + mi*16 + lr;
                afr[mi][0] = __float_as_uint(As[(r  )*36 + k8 + lc    ]);
                afr[mi][1] = __float_as_uint(As[(r+8)*36 + k8 + lc    ]);
                afr[mi][2] = __float_as_uint(As[(r  )*36 + k8 + lc + 4]);
                afr[mi][3] = __float_as_uint(As[(r+8)*36 + k8 + lc + 4]);
            }
            uint32_t bfr[4][2];
            #pragma unroll
            for (int ni = 0; ni < 4; ni++) {
                int n = wn + ni*8 + lr;
                bfr[ni][0] = __float_as_uint(Bs[n*36 + k8 + lc    ]);
                bfr[ni][1] = __float_as_uint(Bs[n*36 + k8 + lc + 4]);
            }
            #pragma unroll
            for (int mi = 0; mi < 2; mi++)
                #pragma unroll
                for (int ni = 0; ni < 4; ni++)
                    mma_tf32(acc[mi][ni], afr[mi], bfr[ni]);
        }
    }
    // epilogue: mask + gate emit
    size_t base = (size_t)b*Nc*Nc;
    #pragma unroll
    for (int mi = 0; mi < 2; mi++) {
        #pragma unroll
        for (int ni = 0; ni < 4; ni++) {
            #pragma unroll
            for (int half = 0; half < 2; half++) {
                int li = wm + mi*16 + lr + half*8;
                int gi = it*64 + li;
                int lj = wn + ni*8 + lc*2;
                int gj = jt*128 + lj;
                float a0 = acc[mi][ni][half*2], a1 = acc[mi][ni][half*2+1];
                bool same = (gi >> 4) == (gj >> 4);
                float m1a = (!same && a0 > 0.5f) ? __fdividef(a0, fmaf(egi1s[li], egj1s[lj], 1.f)) : 0.f;
                float m1b = (!same && a1 > 0.5f) ? __fdividef(a1, fmaf(egi1s[li], egj1s[lj+1], 1.f)) : 0.f;
                float m2a = (a0 > 0.3f) ? __fdividef(a0, fmaf(egi2s[li], egj2s[lj], 1.f)) : 0.f;
                float m2b = (a1 > 0.3f) ? __fdividef(a1, fmaf(egi2s[li], egj2s[lj+1], 1.f)) : 0.f;
                size_t ro = base + (size_t)gi*Nc + gj;
                *(float2*)&d_adjm1[ro] = make_float2(m1a, m1b);
                *(float2*)&d_adjm2[ro] = make_float2(m2a, m2b);
                if (same) {
                    float m0a = (a0 > 0.7f) ? __fdividef(a0, fmaf(egi0s[li], egj0s[lj], 1.f)) : 0.f;
                    float m0b = (a1 > 0.7f) ? __fdividef(a1, fmaf(egi0s[li], egj0s[lj+1], 1.f)) : 0.f;
                    *(float2*)&d_diagm[b*16384 + gi*16 + (gj & 15)] = make_float2(m0a, m0b);
                }
            }
        }
    }
}

// ==================== combined root+nbr GEMM (BM=64, dbuf) ====================
__global__ void __launch_bounds__(256) k_gemm2(const float* __restrict__ Wr, const float* __restrict__ Wn)
{
    extern __shared__ float sm[];
    float* Xs = sm;
    float* Ws = sm + 2*32*68;
    int t = threadIdx.x;
    int y = blockIdx.y; int w = (y >= 3); int s = w ? y-3 : y;
    int row0 = blockIdx.x * 64;
    const float* Wp = (w ? Wn : Wr) + s*Cc*Cc;
    float* Yp = (w ? d_Xnbr : d_Xroot) + (size_t)s*2048*Cc;
    int xr = t >> 2, xk = (t & 3)*8;
    int wk = t >> 3, wc = (t & 7)*16;
    const float* xg = d_feats + (size_t)(row0 + xr)*Cc + xk;
    const float* wg = Wp + (size_t)wk*Cc + wc;
    {
        float4 a0 = *(const float4*)xg, a1 = *(const float4*)(xg+4);
        float* xd = Xs + xr;
        xd[(xk+0)*68]=a0.x; xd[(xk+1)*68]=a0.y; xd[(xk+2)*68]=a0.z; xd[(xk+3)*68]=a0.w;
        xd[(xk+4)*68]=a1.x; xd[(xk+5)*68]=a1.y; xd[(xk+6)*68]=a1.z; xd[(xk+7)*68]=a1.w;
        float* wd = Ws + wk*132 + wc;
        *(float4*)(wd  ) = *(const float4*)(wg  );
        *(float4*)(wd+4) = *(const float4*)(wg+4);
        *(float4*)(wd+8) = *(const float4*)(wg+8);
        *(float4*)(wd+12)= *(const float4*)(wg+12);
    }
    __syncthreads();
    int tx = t & 31, ty = t >> 5;
    float acc[8][4] = {};
    #pragma unroll
    for (int kb = 0; kb < 4; kb++) {
        int buf = kb & 1;
        float4 pa0, pa1, pw0, pw1, pw2, pw3;
        if (kb < 3) {
            pa0 = *(const float4*)(xg + (kb+1)*32);
            pa1 = *(const float4*)(xg + (kb+1)*32 + 4);
            const float* wn = wg + (size_t)(kb+1)*32*Cc;
            pw0 = *(const float4*)(wn); pw1 = *(const float4*)(wn+4);
            pw2 = *(const float4*)(wn+8); pw3 = *(const float4*)(wn+12);
        }
        const float* Xb = Xs + buf*(32*68);
        const float* Wb = Ws + buf*(32*132);
        #pragma unroll
        for (int k = 0; k < 32; k++) {
            float4 a0 = *(const float4*)&Xb[k*68 + ty*8];
            float4 a1 = *(const float4*)&Xb[k*68 + ty*8 + 4];
            float4 bv = *(const float4*)&Wb[k*132 + tx*4];
            float aa[8] = {a0.x,a0.y,a0.z,a0.w,a1.x,a1.y,a1.z,a1.w};
            float bb[4] = {bv.x,bv.y,bv.z,bv.w};
            #pragma unroll
            for (int i = 0; i < 8; i++)
                #pragma unroll
                for (int j = 0; j < 4; j++)
                    acc[i][j] = fmaf(aa[i], bb[j], acc[i][j]);
        }
        if (kb < 3) {
            int nb = buf ^ 1;
            float* xd = Xs + nb*(32*68) + xr;
            xd[(xk+0)*68]=pa0.x; xd[(xk+1)*68]=pa0.y; xd[(xk+2)*68]=pa0.z; xd[(xk+3)*68]=pa0.w;
            xd[(xk+4)*68]=pa1.x; xd[(xk+5)*68]=pa1.y; xd[(xk+6)*68]=pa1.z; xd[(xk+7)*68]=pa1.w;
            float* wd = Ws + nb*(32*132) + wk*132 + wc;
            *(float4*)(wd  ) = pw0; *(float4*)(wd+4) = pw1;
            *(float4*)(wd+8) = pw2; *(float4*)(wd+12)= pw3;
            __syncthreads();
        }
    }
    #pragma unroll
    for (int i = 0; i < 8; i++) {
        int r = row0 + ty*8 + i;
        *(float4*)&Yp[(size_t)r*Cc + tx*4]
            = make_float4(acc[i][0],acc[i][1],acc[i][2],acc[i][3]);
    }
}

// ==================== s=1,2 aggregation: tf32 mma, kc=8 + register prefetch ====================
// C[64,128] += A[64,128] @ B[128,128]; grid (16 m, 4 pair, 8 kc) = 512 blocks
__global__ void __launch_bounds__(256) k_agg()
{
    __shared__ float As[64*36];     // [m][k]
    __shared__ float Bs[128*36];    // [n][k]
    int t = threadIdx.x;
    int i0 = blockIdx.x * 64;
    int y = blockIdx.y;
    int s = 1 + (y >> 1), b = y & 1;
    int kc = blockIdx.z;            // 0..7, K=128 chunk
    size_t fb = ((size_t)s*2048 + b*1024)*Cc;
    const float* Asrc = (s == 1 ? d_adjm1 : d_adjm2) + (size_t)b*Nc*Nc;
    int warp = t >> 5, lane = t & 31;
    int wm = (warp >> 2)*32, wn = (warp & 3)*32;
    int lr = lane >> 2, lc = lane & 3;
    float acc[2][4][4];
    #pragma unroll
    for (int mi = 0; mi < 2; mi++)
        #pragma unroll
        for (int ni = 0; ni < 4; ni++)
            #pragma unroll
            for (int q = 0; q < 4; q++) acc[mi][ni][q] = 0.f;

    int am = t >> 2, ak0 = (t & 3)*8;
    int bj = t & 31, bc0 = (t >> 5)*16;
    const float* asrc0 = Asrc + (size_t)(i0 + am)*Nc + kc*128 + ak0;
    const float* bsrc0 = d_Xnbr + fb + (size_t)(kc*128 + bj)*Cc + bc0;

    // preload first stage into registers
    float4 pa0 = *(const float4*)asrc0, pa1 = *(const float4*)(asrc0 + 4);
    float4 pb0 = *(const float4*)(bsrc0), pb1 = *(const float4*)(bsrc0 + 4),
           pb2 = *(const float4*)(bsrc0 + 8), pb3 = *(const float4*)(bsrc0 + 12);

    for (int ks = 0; ks < 128; ks += 32) {
        __syncthreads();    // prior MMAs done reading smem
        {   // store staged A
            float* dst = As + am*36 + ak0;
            dst[0] = __uint_as_float(f2tf32(pa0.x)); dst[1] = __uint_as_float(f2tf32(pa0.y));
            dst[2] = __uint_as_float(f2tf32(pa0.z)); dst[3] = __uint_as_float(f2tf32(pa0.w));
            dst[4] = __uint_as_float(f2tf32(pa1.x)); dst[5] = __uint_as_float(f2tf32(pa1.y));
            dst[6] = __uint_as_float(f2tf32(pa1.z)); dst[7] = __uint_as_float(f2tf32(pa1.w));
        }
        {   // store staged B (transposed)
            Bs[(bc0+ 0)*36 + bj] = __uint_as_float(f2tf32(pb0.x));
            Bs[(bc0+ 1)*36 + bj] = __uint_as_float(f2tf32(pb0.y));
            Bs[(bc0+ 2)*36 + bj] = __uint_as_float(f2tf32(pb0.z));
            Bs[(bc0+ 3)*36 + bj] = __uint_as_float(f2tf32(pb0.w));
            Bs[(bc0+ 4)*36 + bj] = __uint_as_float(f2tf32(pb1.x));
            Bs[(bc0+ 5)*36 + bj] = __uint_as_float(f2tf32(pb1.y));
            Bs[(bc0+ 6)*36 + bj] = __uint_as_float(f2tf32(pb1.z));
            Bs[(bc0+ 7)*36 + bj] = __uint_as_float(f2tf32(pb1.w));
            Bs[(bc0+ 8)*36 + bj] = __uint_as_float(f2tf32(pb2.x));
            Bs[(bc0+ 9)*36 + bj] = __uint_as_float(f2tf32(pb2.y));
            Bs[(bc0+10)*36 + bj] = __uint_as_float(f2tf32(pb2.z));
            Bs[(bc0+11)*36 + bj] = __uint_as_float(f2tf32(pb2.w));
            Bs[(bc0+12)*36 + bj] = __uint_as_float(f2tf32(pb3.x));
            Bs[(bc0+13)*36 + bj] = __uint_as_float(f2tf32(pb3.y));
            Bs[(bc0+14)*36 + bj] = __uint_as_float(f2tf32(pb3.z));
            Bs[(bc0+15)*36 + bj] = __uint_as_float(f2tf32(pb3.w));
        }
        __syncthreads();
        // prefetch next stage (latency hides behind MMAs)
        if (ks < 96) {
            pa0 = *(const float4*)(asrc0 + ks + 32);
            pa1 = *(const float4*)(asrc0 + ks + 36);
            const float* bn = bsrc0 + (size_t)(ks + 32)*Cc;
            pb0 = *(const float4*)(bn); pb1 = *(const float4*)(bn + 4);
            pb2 = *(const float4*)(bn + 8); pb3 = *(const float4*)(bn + 12);
        }
        #pragma unroll
        for (int k8 = 0; k8 < 32; k8 += 8) {
            uint32_t afr[2][4];
            #pragma unroll
            for (int mi = 0; mi < 2; mi++) {
                int r = wm + mi*16 + lr;
                afr[mi][0] = __float_as_uint(As[(r  )*36 + k8 + lc    ]);
                afr[mi][1] = __float_as_uint(As[(r+8)*36 + k8 + lc    ]);
                afr[mi][2] = __float_as_uint(As[(r  )*36 + k8 + lc + 4]);
                afr[mi][3] = __float_as_uint(As[(r+8)*36 + k8 + lc + 4]);
            }
            uint32_t bfr[4][2];
            #pragma unroll
            for (int ni = 0; ni < 4; ni++) {
                int n = wn + ni*8 + lr;
                bfr[ni][0] = __float_as_uint(Bs[n*36 + k8 + lc    ]);
                bfr[ni][1] = __float_as_uint(Bs[n*36 + k8 + lc + 4]);
            }
            #pragma unroll
            for (int mi = 0; mi < 2; mi++)
                #pragma unroll
                for (int ni = 0; ni < 4; ni++)
                    mma_tf32(acc[mi][ni], afr[mi], bfr[ni]);
        }
    }
    size_t pb = (size_t)y*1048576 + (size_t)kc*131072;
    #pragma unroll
    for (int mi = 0; mi < 2; mi++) {
        #pragma unroll
        for (int ni = 0; ni < 4; ni++) {
            int r0 = i0 + wm + mi*16 + lr;
            int col = wn + ni*8 + lc*2;
            *(float2*)&d_convp[pb + (size_t)r0*Cc + col]
                = make_float2(acc[mi][ni][0], acc[mi][ni][1]);
            *(float2*)&d_convp[pb + (size_t)(r0+8)*Cc + col]
                = make_float2(acc[mi][ni][2], acc[mi][ni][3]);
        }
    }
}

// ==================== combine partials + BN partial stats (+ s=0 diag agg) ====================
// grid (3, 128), 128 threads; each part covers 16 rows
__global__ void k_comb()
{
    int s = blockIdx.x, part = blockIdx.y, t = threadIdx.x;
    float su = 0.f, sq = 0.f;
    int rbase = part*16;
    if (s == 0) {
        __shared__ float Xn[16][129];
        __shared__ float Am[16][17];
        int b = rbase >> 10, n0 = rbase & 1023;
        #pragma unroll
        for (int j2 = 0; j2 < 16; j2++)
            Xn[j2][t] = d_Xnbr[((size_t)b*1024 + n0 + j2)*Cc + t];
        #pragma unroll
        for (int l = 0; l < 2; l++) {
            int id = t + l*128;
            int i = id >> 4, j = id & 15;
            Am[i][j] = d_diagm[b*16384 + (n0 + i)*16 + j];
        }
        __syncthreads();
        for (int r0 = 0; r0 < 16; r0++) {
            int rr = rbase + r0;
            size_t ci = (size_t)rr*Cc + t;
            float v = d_Xroot[ci];
            #pragma unroll
            for (int j = 0; j < 16; j++)
                v = fmaf(Am[r0][j], Xn[j][t], v);
            d_conv[ci] = v;
            su += v; sq = fmaf(v, v, sq);
        }
    } else {
        for (int r0 = 0; r0 < 16; r0++) {
            int rr = rbase + r0;
            size_t ci = ((size_t)s*2048 + rr)*Cc + t;
            int b = rr >> 10, n = rr & 1023;
            size_t pbb = ((size_t)(s-1)*2 + b)*1048576 + (size_t)n*Cc + t;
            float v = d_Xroot[ci];
            #pragma unroll
            for (int kc2 = 0; kc2 < 8; kc2++) v += d_convp[pbb + (size_t)kc2*131072];
            d_conv[ci] = v;
            su += v; sq = fmaf(v, v, sq);
        }
    }
    d_psum[(s*128 + part)*Cc + t] = su;
    d_psq [(s*128 + part)*Cc + t] = sq;
}

// ==================== att GEMM ====================
__global__ void __launch_bounds__(256) k_attgemm(const float* __restrict__ attW, const float* __restrict__ attb,
                          const float* __restrict__ gamma, const float* __restrict__ beta)
{
    extern __shared__ float sm[];
    float* Xs = sm;
    float* Ws = sm + 2*32*68;
    float* scl = sm + 12800;
    float* sft = scl + 128;
    int t = threadIdx.x;
    int row0 = blockIdx.x * 64;
    int s = row0 >> 11;
    if (t < 128) {
        float su = 0.f, sq = 0.f;
        #pragma unroll 8
        for (int p = 0; p < 128; p++) {
            su += d_psum[(s*128+p)*Cc + t];
            sq += d_psq [(s*128+p)*Cc + t];
        }
        float mu = su / 2048.f;
        float va = sq / 2048.f - mu*mu;
        float sc = gamma[s*Cc + t]*rsqrtf(va + 1e-5f);
        scl[t] = sc;
        sft[t] = beta[s*Cc + t] - mu*sc;
    }
    __syncthreads();
    const float* Wp = attW + s*Cc*Cc;
    int xr = t >> 2, xk = (t & 3)*8;
    int wk = t >> 3, wc = (t & 7)*16;
    int fr = (row0 + xr) & 2047;
    const float* cg = d_conv + (size_t)(row0 + xr)*Cc + xk;
    const float* fg = d_feats + (size_t)fr*Cc + xk;
    const float* wg = Wp + (size_t)wk*Cc + wc;
    {
        float4 c0 = *(const float4*)cg, c1 = *(const float4*)(cg+4);
        float4 f0 = *(const float4*)fg, f1 = *(const float4*)(fg+4);
        float* xd = Xs + xr;
        xd[(xk+0)*68] = c0.x*scl[xk+0]+sft[xk+0]+f0.x;
        xd[(xk+1)*68] = c0.y*scl[xk+1]+sft[xk+1]+f0.y;
        xd[(xk+2)*68] = c0.z*scl[xk+2]+sft[xk+2]+f0.z;
        xd[(xk+3)*68] = c0.w*scl[xk+3]+sft[xk+3]+f0.w;
        xd[(xk+4)*68] = c1.x*scl[xk+4]+sft[xk+4]+f1.x;
        xd[(xk+5)*68] = c1.y*scl[xk+5]+sft[xk+5]+f1.y;
        xd[(xk+6)*68] = c1.z*scl[xk+6]+sft[xk+6]+f1.z;
        xd[(xk+7)*68] = c1.w*scl[xk+7]+sft[xk+7]+f1.w;
        float* wd = Ws + wk*132 + wc;
        *(float4*)(wd  ) = *(const float4*)(wg  );
        *(float4*)(wd+4) = *(const float4*)(wg+4);
        *(float4*)(wd+8) = *(const float4*)(wg+8);
        *(float4*)(wd+12)= *(const float4*)(wg+12);
    }
    __syncthreads();
    int tx = t & 31, ty = t >> 5;
    float acc[8][4] = {};
    #pragma unroll
    for (int kb = 0; kb < 4; kb++) {
        int buf = kb & 1;
        float4 pc0, pc1, pf0, pf1, pw0, pw1, pw2, pw3;
        if (kb < 3) {
            pc0 = *(const float4*)(cg + (kb+1)*32);
            pc1 = *(const float4*)(cg + (kb+1)*32 + 4);
            pf0 = *(const float4*)(fg + (kb+1)*32);
            pf1 = *(const float4*)(fg + (kb+1)*32 + 4);
            const float* wn = wg + (size_t)(kb+1)*32*Cc;
            pw0 = *(const float4*)(wn); pw1 = *(const float4*)(wn+4);
            pw2 = *(const float4*)(wn+8); pw3 = *(const float4*)(wn+12);
        }
        const float* Xb = Xs + buf*(32*68);
        const float* Wb = Ws + buf*(32*132);
        #pragma unroll
        for (int k = 0; k < 32; k++) {
            float4 a0 = *(const float4*)&Xb[k*68 + ty*8];
            float4 a1 = *(const float4*)&Xb[k*68 + ty*8 + 4];
            float4 bv = *(const float4*)&Wb[k*132 + tx*4];
            float aa[8] = {a0.x,a0.y,a0.z,a0.w,a1.x,a1.y,a1.z,a1.w};
            float bb[4] = {bv.x,bv.y,bv.z,bv.w};
            #pragma unroll
            for (int i = 0; i < 8; i++)
                #pragma unroll
                for (int j = 0; j < 4; j++)
                    acc[i][j] = fmaf(aa[i], bb[j], acc[i][j]);
        }
        if (kb < 3) {
            int nb = buf ^ 1;
            int kbase = (kb+1)*32;
            float* xd = Xs + nb*(32*68) + xr;
            xd[(xk+0)*68] = pc0.x*scl[kbase+xk+0]+sft[kbase+xk+0]+pf0.x;
            xd[(xk+1)*68] = pc0.y*scl[kbase+xk+1]+sft[kbase+xk+1]+pf0.y;
            xd[(xk+2)*68] = pc0.z*scl[kbase+xk+2]+sft[kbase+xk+2]+pf0.z;
            xd[(xk+3)*68] = pc0.w*scl[kbase+xk+3]+sft[kbase+xk+3]+pf0.w;
            xd[(xk+4)*68] = pc1.x*scl[kbase+xk+4]+sft[kbase+xk+4]+pf1.x;
            xd[(xk+5)*68] = pc1.y*scl[kbase+xk+5]+sft[kbase+xk+5]+pf1.y;
            xd[(xk+6)*68] = pc1.z*scl[kbase+xk+6]+sft[kbase+xk+6]+pf1.z;
            xd[(xk+7)*68] = pc1.w*scl[kbase+xk+7]+sft[kbase+xk+7]+pf1.w;
            float* wd = Ws + nb*(32*132) + wk*132 + wc;
            *(float4*)(wd  ) = pw0; *(float4*)(wd+4) = pw1;
            *(float4*)(wd+8) = pw2; *(float4*)(wd+12)= pw3;
            __syncthreads();
        }
    }
    float colmax[4] = {-3.4e38f,-3.4e38f,-3.4e38f,-3.4e38f};
    #pragma unroll
    for (int i = 0; i < 8; i++) {
        int row = row0 + ty*8 + i;
        int frr = row & 2047;
        float4 cv = *(const float4*)&d_conv[(size_t)row*Cc + tx*4];
        float4 fv = *(const float4*)&d_feats[(size_t)frr*Cc + tx*4];
        float cva[4] = {cv.x,cv.y,cv.z,cv.w};
        float fva[4] = {fv.x,fv.y,fv.z,fv.w};
        float o[4];
        #pragma unroll
        for (int j = 0; j < 4; j++) {
            int c = tx*4 + j;
            float v = acc[i][j] + attb[s*Cc + c];
            float hv = cva[j]*scl[c] + sft[c] + fva[j];
            float yv = fmaxf(sigf(v)*hv, 0.f);
            o[j] = yv;
            colmax[j] = fmaxf(colmax[j], yv);
        }
        *(float4*)&d_y[(size_t)row*Cc + tx*4] = make_float4(o[0],o[1],o[2],o[3]);
    }
    __syncthreads();
    float* pm = sm;
    #pragma unroll
    for (int j = 0; j < 4; j++) pm[ty*132 + tx*4 + j] = colmax[j];
    __syncthreads();
    if (t < 128) {
        float m = -3.4e38f;
        #pragma unroll
        for (int q = 0; q < 8; q++) m = fmaxf(m, pm[q*132 + t]);
        int bb = (row0 >> 10) & 1, tl = (row0 & 1023) >> 6;
        d_poolp[((s*2 + bb)*16 + tl)*Cc + t] = m;
    }
}

// ==================== mlp ====================
__global__ void k_mlp(const float* __restrict__ W1, const float* __restrict__ b1,
                      const float* __restrict__ W2, const float* __restrict__ b2)
{
    int sb = blockIdx.x, t = threadIdx.x;
    int s = sb >> 1;
    __shared__ float p[128], t1[128];
    float m = -3.4e38f;
    #pragma unroll
    for (int ch = 0; ch < 16; ch++) m = fmaxf(m, d_poolp[(sb*16 + ch)*Cc + t]);
    p[t] = m;
    __syncthreads();
    float acc = b1[s*Cc + t];
    #pragma unroll 8
    for (int k = 0; k < 128; k++) acc = fmaf(p[k], W1[s*Cc*Cc + k*Cc + t], acc);
    t1[t] = fmaxf(acc, 0.f);
    __syncthreads();
    float acc2 = b2[s*Cc + t];
    #pragma unroll 8
    for (int k = 0; k < 128; k++) acc2 = fmaf(t1[k], W2[s*Cc*Cc + k*Cc + t], acc2);
    d_pools2[sb*Cc + t] = sigf(acc2);
}

// ==================== final GEMM: fused softmax-mix X + Aw prologue ====================
__global__ void __launch_bounds__(256) k_fusegemm(const float* __restrict__ W, const float* __restrict__ bias,
                           const float* __restrict__ lw, const float* __restrict__ lb)
{
    extern __shared__ float sm[];
    float* Xs = sm;
    float* Ws = sm + 2*32*68;
    float* p2s = sm + 12800;
    float* aw  = p2s + 384;
    int t = threadIdx.x;
    int row0 = blockIdx.x * 64;
    int b = row0 >> 10;
    for (int i = t; i < 384; i += 256)
        p2s[i] = d_pools2[((i >> 7)*2 + b)*Cc + (i & 127)];
    __syncthreads();
    if (t < 32) {
        float av[3];
        #pragma unroll
        for (int s = 0; s < 3; s++) {
            float r = 0.f;
            #pragma unroll
            for (int q = 0; q < 4; q++) {
                int c = t + q*32;
                r = fmaf(p2s[s*128 + c], lw[s*Cc + c], r);
            }
            #pragma unroll
            for (int o = 16; o; o >>= 1) r += __shfl_xor_sync(0xffffffffu, r, o);
            av[s] = r + lb[s];
        }
        if (t == 0) {
            float m = fmaxf(av[0], fmaxf(av[1], av[2]));
            float e0 = __expf(av[0]-m), e1 = __expf(av[1]-m), e2 = __expf(av[2]-m);
            float inv = 1.f/(e0+e1+e2);
            aw[0] = e0*inv; aw[1] = e1*inv; aw[2] = e2*inv;
        }
    }
    __syncthreads();
    float aw0 = aw[0], aw1 = aw[1], aw2 = aw[2];
    int xr = t >> 2, xk = (t & 3)*8;
    int wk = t >> 3, wc = (t & 7)*16;
    const float* y0 = d_y + (size_t)(row0 + xr)*Cc + xk;
    const float* y1 = y0 + (size_t)2048*Cc;
    const float* y2 = y1 + (size_t)2048*Cc;
    const float* wg = W + (size_t)wk*Cc + wc;
    #define FUSE_XLOAD(dst, off) { \
        float4 v0 = *(const float4*)(y0+(off)), v0b = *(const float4*)(y0+(off)+4); \
        float4 v1 = *(const float4*)(y1+(off)), v1b = *(const float4*)(y1+(off)+4); \
        float4 v2 = *(const float4*)(y2+(off)), v2b = *(const float4*)(y2+(off)+4); \
        int kb0 = (off) + xk; \
        dst[(xk+0)*68] = aw0*p2s[kb0+0]*v0.x + aw1*p2s[128+kb0+0]*v1.x + aw2*p2s[256+kb0+0]*v2.x; \
        dst[(xk+1)*68] = aw0*p2s[kb0+1]*v0.y + aw1*p2s[128+kb0+1]*v1.y + aw2*p2s[256+kb0+1]*v2.y; \
        dst[(xk+2)*68] = aw0*p2s[kb0+2]*v0.z + aw1*p2s[128+kb0+2]*v1.z + aw2*p2s[256+kb0+2]*v2.z; \
        dst[(xk+3)*68] = aw0*p2s[kb0+3]*v0.w + aw1*p2s[128+kb0+3]*v1.w + aw2*p2s[256+kb0+3]*v2.w; \
        dst[(xk+4)*68] = aw0*p2s[kb0+4]*v0b.x + aw1*p2s[128+kb0+4]*v1b.x + aw2*p2s[256+kb0+4]*v2b.x; \
        dst[(xk+5)*68] = aw0*p2s[kb0+5]*v0b.y + aw1*p2s[128+kb0+5]*v1b.y + aw2*p2s[256+kb0+5]*v2b.y; \
        dst[(xk+6)*68] = aw0*p2s[kb0+6]*v0b.z + aw1*p2s[128+kb0+6]*v1b.z + aw2*p2s[256+kb0+6]*v2b.z; \
        dst[(xk+7)*68] = aw0*p2s[kb0+7]*v0b.w + aw1*p2s[128+kb0+7]*v1b.w + aw2*p2s[256+kb0+7]*v2b.w; \
    }
    {
        float* xd = Xs + xr;
        FUSE_XLOAD(xd, 0);
        float* wd = Ws + wk*132 + wc;
        *(float4*)(wd  ) = *(const float4*)(wg  );
        *(float4*)(wd+4) = *(const float4*)(wg+4);
        *(float4*)(wd+8) = *(const float4*)(wg+8);
        *(float4*)(wd+12)= *(const float4*)(wg+12);
    }
    __syncthreads();
    int tx = t & 31, ty = t >> 5;
    float acc[8][4] = {};
    #pragma unroll
    for (int kb = 0; kb < 4; kb++) {
        int buf = kb & 1;
        const float* Xb = Xs + buf*(32*68);
        const float* Wb = Ws + buf*(32*132);
        #pragma unroll
        for (int k = 0; k < 32; k++) {
            float4 a0 = *(const float4*)&Xb[k*68 + ty*8];
            float4 a1 = *(const float4*)&Xb[k*68 + ty*8 + 4];
            float4 bv = *(const float4*)&Wb[k*132 + tx*4];
            float aa[8] = {a0.x,a0.y,a0.z,a0.w,a1.x,a1.y,a1.z,a1.w};
            float bb[4] = {bv.x,bv.y,bv.z,bv.w};
            #pragma unroll
            for (int i = 0; i < 8; i++)
                #pragma unroll
                for (int j = 0; j < 4; j++)
                    acc[i][j] = fmaf(aa[i], bb[j], acc[i][j]);
        }
        if (kb < 3) {
            __syncthreads();
            int nb = buf ^ 1;
            float* xd = Xs + nb*(32*68) + xr;
            FUSE_XLOAD(xd, (kb+1)*32);
            float* wd = Ws + nb*(32*132) + wk*132 + wc;
            const float* wn = wg + (size_t)(kb+1)*32*Cc;
            *(float4*)(wd  ) = *(const float4*)(wn  );
            *(float4*)(wd+4) = *(const float4*)(wn+4);
            *(float4*)(wd+8) = *(const float4*)(wn+8);
            *(float4*)(wd+12)= *(const float4*)(wn+12);
            __syncthreads();
        }
    }
    #pragma unroll
    for (int i = 0; i < 8; i++) {
        int r = row0 + ty*8 + i;
        float o[4];
        #pragma unroll
        for (int j = 0; j < 4; j++) o[j] = acc[i][j] + bias[tx*4 + j];
        *(float4*)&d_yfin[(size_t)r*Cc + tx*4] = make_float4(o[0],o[1],o[2],o[3]);
    }
}

// ==================== reprojection + residual ====================
__global__ void k_reproj(const float* __restrict__ x, float* __restrict__ out)
{
    __shared__ float yf[16*64];
    int blk = blockIdx.x, b = blockIdx.y, ch = blockIdx.z, t = threadIdx.x;
    int c0 = ch*64;
    #pragma unroll
    for (int l = 0; l < 4; l++) {
        int idx = t + l*256;
        yf[idx] = d_yfin[((size_t)b*1024 + blk*16 + (idx>>6))*Cc + c0 + (idx & 63)];
    }
    __syncthreads();
    float q[16];
    #pragma unroll
    for (int k = 0; k < 16; k++)
        q[k] = d_Q[(((size_t)b*NBLKc + blk)*BNODc + k)*NPc + t];
    int bi = blk >> 3, bj = blk & 7, hi = t >> 4, wi = t & 15;
    size_t base = (size_t)b*Cc*HWc + (size_t)c0*HWc + (size_t)(bi*16+hi)*Wc + (bj*16+wi);
    #pragma unroll 4
    for (int c4 = 0; c4 < 16; c4++) {
        float4 a = make_float4(0.f,0.f,0.f,0.f);
        #pragma unroll
        for (int k = 0; k < 16; k++) {
            float4 yv = *(float4*)&yf[k*64 + c4*4];
            a.x = fmaf(q[k], yv.x, a.x);
            a.y = fmaf(q[k], yv.y, a.y);
            a.z = fmaf(q[k], yv.z, a.z);
            a.w = fmaf(q[k], yv.w, a.w);
        }
        int c = c4*4;
        out[base + (size_t)(c+0)*HWc] = x[base + (size_t)(c+0)*HWc] + a.x;
        out[base + (size_t)(c+1)*HWc] = x[base + (size_t)(c+1)*HWc] + a.y;
        out[base + (size_t)(c+2)*HWc] = x[base + (size_t)(c+2)*HWc] + a.z;
        out[base + (size_t)(c+3)*HWc] = x[base + (size_t)(c+3)*HWc] + a.w;
    }
}

extern "C" void kernel_launch(void* const* d_in, const int* in_sizes, int n_in,
                              void* d_out, int out_size)
{
    const float* x        = (const float*)d_in[0];
    const float* anchor   = (const float*)d_in[1];
    const float* sigma    = (const float*)d_in[2];
    const float* W_root   = (const float*)d_in[3];
    const float* W_nbr    = (const float*)d_in[4];
    const float* wg_src   = (const float*)d_in[5];
    const float* wg_dst   = (const float*)d_in[6];
    const float* b_gate   = (const float*)d_in[7];
    const float* bn_gamma = (const float*)d_in[8];
    const float* bn_beta  = (const float*)d_in[9];
    const float* att_W    = (const float*)d_in[10];
    const float* att_b    = (const float*)d_in[11];
    const float* mlp_W1   = (const float*)d_in[12];
    const float* mlp_b1   = (const float*)d_in[13];
    const float* mlp_W2   = (const float*)d_in[14];
    const float* mlp_b2   = (const float*)d_in[15];
    const float* lineA_w  = (const float*)d_in[16];
    const float* lineA_b  = (const float*)d_in[17];
    const float* lineFu_W = (const float*)d_in[18];
    const float* lineFu_b = (const float*)d_in[19];
    float* out = (float*)d_out;

    cudaFuncSetAttribute(k_proj,     cudaFuncAttributeMaxDynamicSharedMemorySize, PROJ_SMEM);
    cudaFuncSetAttribute(k_gemm2,    cudaFuncAttributeMaxDynamicSharedMemorySize, G64_SMEM);
    cudaFuncSetAttribute(k_attgemm,  cudaFuncAttributeMaxDynamicSharedMemorySize, ATT_SMEM);
    cudaFuncSetAttribute(k_fusegemm, cudaFuncAttributeMaxDynamicSharedMemorySize, FUSE_SMEM);

    k_proj<<<dim3(NBLKc, Bc), 256, PROJ_SMEM>>>(x, anchor, sigma, wg_src, wg_dst, b_gate);
    k_adj<<<dim3(8, 16, Bc), 256>>>();
    k_gemm2<<<dim3(32, 6), 256, G64_SMEM>>>(W_root, W_nbr);
    k_agg<<<dim3(16, 4, 8), 256>>>();
    k_comb<<<dim3(3, 128), 128>>>();
    k_attgemm<<<96, 256, ATT_SMEM>>>(att_W, att_b, bn_gamma, bn_beta);
    k_mlp<<<6, 128>>>(mlp_W1, mlp_b1, mlp_W2, mlp_b2);
    k_fusegemm<<<32, 256, FUSE_SMEM>>>(lineFu_W, lineFu_b, lineA_w, lineA_b);
    k_reproj<<<dim3(NBLKc, Bc, 2), 256>>>(x, out);
}

// round 17
// speedup vs baseline: 1.1202x; 1.0152x over previous
#include <cuda_runtime.h>
#include <math.h>
#include <stdint.h>

#define Bc 2
#define Cc 128
#define Hc 128
#define Wc 128
#define NBLKc 64
#define BNODc 16
#define Nc 1024
#define NPc 256
#define HWc (Hc*Wc)

#define PROJ_SMEM 176512
#define G64_SMEM  51200
#define AGG_SMEM  55296
#define ATT_SMEM  52224
#define FUSE_SMEM 52768

// ---------------- scratch ----------------
__device__ float d_Q[Bc*NBLKc*BNODc*NPc];
__device__ float d_feats[Bc*Nc*Cc];
__device__ float d_adjm1[(size_t)Bc*Nc*Nc];   // masked+gated, s=1
__device__ float d_adjm2[(size_t)Bc*Nc*Nc];   // masked+gated, s=2
__device__ float d_diagm[Bc*Nc*16];           // masked+gated diag blocks, s=0
__device__ float d_Xnbr[3*Bc*Nc*Cc];
__device__ float d_Xroot[3*Bc*Nc*Cc];
__device__ float d_egi[3*Bc*Nc];      // exp(-(gi + b_gate[s]))
__device__ float d_egj[3*Bc*Nc];      // exp(-gj)
__device__ float d_convp[(size_t)4*4*Nc*Cc];  // [pair(s-1,b)][kc 0..3][n][c]
__device__ float d_conv[3*Bc*Nc*Cc];
__device__ float d_psum[3*128*Cc];
__device__ float d_psq[3*128*Cc];
__device__ float d_y[3*Bc*Nc*Cc];
__device__ float d_poolp[3*2*16*Cc];
__device__ float d_pools2[3*Bc*Cc];
__device__ float d_yfin[Bc*Nc*Cc];

__device__ __forceinline__ float sigf(float z) { return 1.f/(1.f + __expf(-z)); }

__device__ __forceinline__ uint32_t f2tf32(float v) {
    uint32_t r;
    asm("cvt.rna.tf32.f32 %0, %1;" : "=r"(r) : "f"(v));
    return r;
}
__device__ __forceinline__ void mma_tf32(float* c, const uint32_t* a, const uint32_t* b) {
    asm volatile(
        "mma.sync.aligned.m16n8k8.row.col.f32.tf32.tf32.f32 "
        "{%0,%1,%2,%3}, {%4,%5,%6,%7}, {%8,%9}, {%0,%1,%2,%3};\n"
        : "+f"(c[0]), "+f"(c[1]), "+f"(c[2]), "+f"(c[3])
        : "r"(a[0]), "r"(a[1]), "r"(a[2]), "r"(a[3]), "r"(b[0]), "r"(b[1]));
}

// ==================== projection + fused norm/gates (exp form) ====================
__global__ void k_proj(const float* __restrict__ x, const float* __restrict__ anchor,
                       const float* __restrict__ sigma,
                       const float* __restrict__ wsrc, const float* __restrict__ wdst,
                       const float* __restrict__ bgate)
{
    extern __shared__ float sm[];
    float* pix = sm;                                   // [256][129]
    float* sas = sm + 256*129;                         // [16][257]
    float2* ci = (float2*)(sm + 256*129 + 16*257);     // [16][128]: (isig, anc*isig)
    float* Ss  = (float*)(ci + 16*128);                // [16]
    float* vals = Ss + 16;                             // [16][132]
    float* wsd  = vals + 16*132;                       // [6][128]
    int blk = blockIdx.x, b = blockIdx.y;
    int t = threadIdx.x;
    int bi = blk >> 3, bj = blk & 7;
    int hi = t >> 4, wi = t & 15;

    const float* xb = x + (size_t)b*Cc*HWc + (size_t)(bi*16+hi)*Wc + (bj*16+wi);
    #pragma unroll 8
    for (int c = 0; c < Cc; c++) pix[t*129 + c] = xb[(size_t)c*HWc];

    for (int idx = t; idx < BNODc*Cc; idx += 256) {
        float sr = sigma[blk*BNODc*Cc + idx];
        float isg = 1.f + __expf(-sr);                 // 1/sigmoid(sr)
        float an = anchor[blk*BNODc*Cc + idx];
        ci[idx] = make_float2(isg, an*isg);
    }
    for (int i = t; i < 768; i += 256) wsd[i] = (i < 384) ? wsrc[i] : wdst[i-384];
    __syncthreads();

    float lg[16];
    #pragma unroll
    for (int k = 0; k < 16; k++) lg[k] = 0.f;
    for (int c0 = 0; c0 < Cc; c0 += 16) {
        float px[16];
        #pragma unroll
        for (int cc = 0; cc < 16; cc++) px[cc] = pix[t*129 + c0 + cc];
        #pragma unroll
        for (int k = 0; k < 16; k++) {
            float acc = 0.f;
            #pragma unroll
            for (int cc = 0; cc < 16; cc++) {
                float2 v = ci[k*Cc + c0 + cc];
                float d = fmaf(px[cc], v.x, -v.y);
                acc = fmaf(d, d, acc);
            }
            lg[k] += acc;
        }
    }
    float m = -0.5f*lg[0];
    #pragma unroll
    for (int k = 1; k < 16; k++) m = fmaxf(m, -0.5f*lg[k]);
    float sum = 0.f; float e[16];
    #pragma unroll
    for (int k = 0; k < 16; k++) { e[k] = __expf(-0.5f*lg[k] - m); sum += e[k]; }
    float inv = 1.f/sum;
    #pragma unroll
    for (int k = 0; k < 16; k++) {
        float sv = e[k]*inv;
        sas[k*257 + t] = sv;
        d_Q[(((size_t)b*NBLKc + blk)*BNODc + k)*NPc + t] = sv;
    }
    __syncthreads();

    if (t < 16) {
        float s_ = 0.f;
        for (int p = 0; p < 256; p++) s_ += sas[t*257 + p];
        Ss[t] = s_;
    }
    __syncthreads();

    int c = t & 127, kh = t >> 7;
    #pragma unroll
    for (int kk = 0; kk < 8; kk++) {
        int k = kk*2 + kh;
        float acc = 0.f;
        for (int p = 0; p < 256; p++)
            acc = fmaf(sas[k*257 + p], pix[p*129 + c], acc);
        float2 v = ci[k*Cc + c];
        float S = Ss[k];
        vals[k*132 + c] = (v.x*acc - v.y*S) / (S + 1e-9f);
    }
    __syncthreads();

    int wid = t >> 5, lane = t & 31;
    #pragma unroll
    for (int rr = 0; rr < 2; rr++) {
        int k = wid*2 + rr;
        float r[7] = {0.f,0.f,0.f,0.f,0.f,0.f,0.f};
        #pragma unroll
        for (int q = 0; q < 4; q++) {
            int c2 = lane + q*32;
            float v = vals[k*132 + c2];
            r[0] = fmaf(v, v, r[0]);
            #pragma unroll
            for (int s = 0; s < 3; s++) {
                r[1+s] = fmaf(v, wsd[s*128 + c2], r[1+s]);
                r[4+s] = fmaf(v, wsd[(3+s)*128 + c2], r[4+s]);
            }
        }
        #pragma unroll
        for (int o = 16; o; o >>= 1)
            #pragma unroll
            for (int q = 0; q < 7; q++) r[q] += __shfl_xor_sync(0xffffffffu, r[q], o);
        float ninv = 1.f/fmaxf(sqrtf(r[0]), 1e-12f);
        int grow = b*1024 + blk*16 + k;
        #pragma unroll
        for (int q = 0; q < 4; q++) {
            int c2 = lane + q*32;
            d_feats[(size_t)grow*Cc + c2] = vals[k*132 + c2]*ninv;
        }
        if (lane < 3)
            d_egi[lane*2048 + grow] = __expf(-(r[1+lane]*ninv + bgate[lane]));
        else if (lane >= 4 && lane < 7)
            d_egj[(lane-4)*2048 + grow] = __expf(-r[lane]*ninv);
    }
}

// ==================== adj: tf32 mma GEMM + fused mask/gate emit ====================
__global__ void __launch_bounds__(256) k_adj()
{
    __shared__ float As[64*36];     // [m][k]
    __shared__ float Bs[128*36];    // [n][k] (feats rows, direct copy)
    __shared__ float egi0s[64], egi1s[64], egi2s[64];
    __shared__ float egj0s[128], egj1s[128], egj2s[128];
    int t = threadIdx.x;
    int jt = blockIdx.x, it = blockIdx.y, b = blockIdx.z;
    const float* fb = d_feats + (size_t)b*Nc*Cc;
    if (t < 64) {
        egi0s[t] = d_egi[       b*1024 + it*64 + t];
        egi1s[t] = d_egi[2048 + b*1024 + it*64 + t];
        egi2s[t] = d_egi[4096 + b*1024 + it*64 + t];
    } else if (t < 192) {
        int j = t - 64;
        egj0s[j] = d_egj[       b*1024 + jt*128 + j];
        egj1s[j] = d_egj[2048 + b*1024 + jt*128 + j];
        egj2s[j] = d_egj[4096 + b*1024 + jt*128 + j];
    }
    int warp = t >> 5, lane = t & 31;
    int wm = (warp >> 2)*32, wn = (warp & 3)*32;
    int lr = lane >> 2, lc = lane & 3;
    float acc[2][4][4];
    #pragma unroll
    for (int mi = 0; mi < 2; mi++)
        #pragma unroll
        for (int ni = 0; ni < 4; ni++)
            #pragma unroll
            for (int q = 0; q < 4; q++) acc[mi][ni][q] = 0.f;

    int am = t >> 2, ak0 = (t & 3)*8;
    int bn = t >> 1, bk0 = (t & 1)*16;

    for (int ks = 0; ks < 128; ks += 32) {
        __syncthreads();
        {   // A [64][32]
            const float* src = fb + (size_t)(it*64 + am)*Cc + ks + ak0;
            float4 v0 = *(const float4*)src, v1 = *(const float4*)(src + 4);
            float* dst = As + am*36 + ak0;
            dst[0] = __uint_as_float(f2tf32(v0.x)); dst[1] = __uint_as_float(f2tf32(v0.y));
            dst[2] = __uint_as_float(f2tf32(v0.z)); dst[3] = __uint_as_float(f2tf32(v0.w));
            dst[4] = __uint_as_float(f2tf32(v1.x)); dst[5] = __uint_as_float(f2tf32(v1.y));
            dst[6] = __uint_as_float(f2tf32(v1.z)); dst[7] = __uint_as_float(f2tf32(v1.w));
        }
        {   // B [128][32] direct rows
            const float* src = fb + (size_t)(jt*128 + bn)*Cc + ks + bk0;
            float* dst = Bs + bn*36 + bk0;
            #pragma unroll
            for (int q = 0; q < 4; q++) {
                float4 v = *(const float4*)(src + q*4);
                dst[q*4+0] = __uint_as_float(f2tf32(v.x));
                dst[q*4+1] = __uint_as_float(f2tf32(v.y));
                dst[q*4+2] = __uint_as_float(f2tf32(v.z));
                dst[q*4+3] = __uint_as_float(f2tf32(v.w));
            }
        }
        __syncthreads();
        #pragma unroll
        for (int k8 = 0; k8 < 32; k8 += 8) {
            uint32_t afr[2][4];
            #pragma unroll
            for (int mi = 0; mi < 2; mi++) {
                int r = wm + mi*16 + lr;
                afr[mi][0] = __float_as_uint(As[(r  )*36 + k8 + lc    ]);
                afr[mi][1] = __float_as_uint(As[(r+8)*36 + k8 + lc    ]);
                afr[mi][2] = __float_as_uint(As[(r  )*36 + k8 + lc + 4]);
                afr[mi][3] = __float_as_uint(As[(r+8)*36 + k8 + lc + 4]);
            }
            uint32_t bfr[4][2];
            #pragma unroll
            for (int ni = 0; ni < 4; ni++) {
                int n = wn + ni*8 + lr;
                bfr[ni][0] = __float_as_uint(Bs[n*36 + k8 + lc    ]);
                bfr[ni][1] = __float_as_uint(Bs[n*36 + k8 + lc + 4]);
            }
            #pragma unroll
            for (int mi = 0; mi < 2; mi++)
                #pragma unroll
                for (int ni = 0; ni < 4; ni++)
                    mma_tf32(acc[mi][ni], afr[mi], bfr[ni]);
        }
    }
    // epilogue: mask + gate emit
    size_t base = (size_t)b*Nc*Nc;
    #pragma unroll
    for (int mi = 0; mi < 2; mi++) {
        #pragma unroll
        for (int ni = 0; ni < 4; ni++) {
            #pragma unroll
            for (int half = 0; half < 2; half++) {
                int li = wm + mi*16 + lr + half*8;
                int gi = it*64 + li;
                int lj = wn + ni*8 + lc*2;
                int gj = jt*128 + lj;
                float a0 = acc[mi][ni][half*2], a1 = acc[mi][ni][half*2+1];
                bool same = (gi >> 4) == (gj >> 4);
                float m1a = (!same && a0 > 0.5f) ? __fdividef(a0, fmaf(egi1s[li], egj1s[lj], 1.f)) : 0.f;
                float m1b = (!same && a1 > 0.5f) ? __fdividef(a1, fmaf(egi1s[li], egj1s[lj+1], 1.f)) : 0.f;
                float m2a = (a0 > 0.3f) ? __fdividef(a0, fmaf(egi2s[li], egj2s[lj], 1.f)) : 0.f;
                float m2b = (a1 > 0.3f) ? __fdividef(a1, fmaf(egi2s[li], egj2s[lj+1], 1.f)) : 0.f;
                size_t ro = base + (size_t)gi*Nc + gj;
                *(float2*)&d_adjm1[ro] = make_float2(m1a, m1b);
                *(float2*)&d_adjm2[ro] = make_float2(m2a, m2b);
                if (same) {
                    float m0a = (a0 > 0.7f) ? __fdividef(a0, fmaf(egi0s[li], egj0s[lj], 1.f)) : 0.f;
                    float m0b = (a1 > 0.7f) ? __fdividef(a1, fmaf(egi0s[li], egj0s[lj+1], 1.f)) : 0.f;
                    *(float2*)&d_diagm[b*16384 + gi*16 + (gj & 15)] = make_float2(m0a, m0b);
                }
            }
        }
    }
}

// ==================== combined root+nbr GEMM (BM=64, dbuf) ====================
__global__ void __launch_bounds__(256) k_gemm2(const float* __restrict__ Wr, const float* __restrict__ Wn)
{
    extern __shared__ float sm[];
    float* Xs = sm;
    float* Ws = sm + 2*32*68;
    int t = threadIdx.x;
    int y = blockIdx.y; int w = (y >= 3); int s = w ? y-3 : y;
    int row0 = blockIdx.x * 64;
    const float* Wp = (w ? Wn : Wr) + s*Cc*Cc;
    float* Yp = (w ? d_Xnbr : d_Xroot) + (size_t)s*2048*Cc;
    int xr = t >> 2, xk = (t & 3)*8;
    int wk = t >> 3, wc = (t & 7)*16;
    const float* xg = d_feats + (size_t)(row0 + xr)*Cc + xk;
    const float* wg = Wp + (size_t)wk*Cc + wc;
    {
        float4 a0 = *(const float4*)xg, a1 = *(const float4*)(xg+4);
        float* xd = Xs + xr;
        xd[(xk+0)*68]=a0.x; xd[(xk+1)*68]=a0.y; xd[(xk+2)*68]=a0.z; xd[(xk+3)*68]=a0.w;
        xd[(xk+4)*68]=a1.x; xd[(xk+5)*68]=a1.y; xd[(xk+6)*68]=a1.z; xd[(xk+7)*68]=a1.w;
        float* wd = Ws + wk*132 + wc;
        *(float4*)(wd  ) = *(const float4*)(wg  );
        *(float4*)(wd+4) = *(const float4*)(wg+4);
        *(float4*)(wd+8) = *(const float4*)(wg+8);
        *(float4*)(wd+12)= *(const float4*)(wg+12);
    }
    __syncthreads();
    int tx = t & 31, ty = t >> 5;
    float acc[8][4] = {};
    #pragma unroll
    for (int kb = 0; kb < 4; kb++) {
        int buf = kb & 1;
        float4 pa0, pa1, pw0, pw1, pw2, pw3;
        if (kb < 3) {
            pa0 = *(const float4*)(xg + (kb+1)*32);
            pa1 = *(const float4*)(xg + (kb+1)*32 + 4);
            const float* wn = wg + (size_t)(kb+1)*32*Cc;
            pw0 = *(const float4*)(wn); pw1 = *(const float4*)(wn+4);
            pw2 = *(const float4*)(wn+8); pw3 = *(const float4*)(wn+12);
        }
        const float* Xb = Xs + buf*(32*68);
        const float* Wb = Ws + buf*(32*132);
        #pragma unroll
        for (int k = 0; k < 32; k++) {
            float4 a0 = *(const float4*)&Xb[k*68 + ty*8];
            float4 a1 = *(const float4*)&Xb[k*68 + ty*8 + 4];
            float4 bv = *(const float4*)&Wb[k*132 + tx*4];
            float aa[8] = {a0.x,a0.y,a0.z,a0.w,a1.x,a1.y,a1.z,a1.w};
            float bb[4] = {bv.x,bv.y,bv.z,bv.w};
            #pragma unroll
            for (int i = 0; i < 8; i++)
                #pragma unroll
                for (int j = 0; j < 4; j++)
                    acc[i][j] = fmaf(aa[i], bb[j], acc[i][j]);
        }
        if (kb < 3) {
            int nb = buf ^ 1;
            float* xd = Xs + nb*(32*68) + xr;
            xd[(xk+0)*68]=pa0.x; xd[(xk+1)*68]=pa0.y; xd[(xk+2)*68]=pa0.z; xd[(xk+3)*68]=pa0.w;
            xd[(xk+4)*68]=pa1.x; xd[(xk+5)*68]=pa1.y; xd[(xk+6)*68]=pa1.z; xd[(xk+7)*68]=pa1.w;
            float* wd = Ws + nb*(32*132) + wk*132 + wc;
            *(float4*)(wd  ) = pw0; *(float4*)(wd+4) = pw1;
            *(float4*)(wd+8) = pw2; *(float4*)(wd+12)= pw3;
            __syncthreads();
        }
    }
    #pragma unroll
    for (int i = 0; i < 8; i++) {
        int r = row0 + ty*8 + i;
        *(float4*)&Yp[(size_t)r*Cc + tx*4]
            = make_float4(acc[i][0],acc[i][1],acc[i][2],acc[i][3]);
    }
}

// ==================== s=1,2 aggregation: tf32 mma, kc=4, dbuf smem + reg prefetch ====================
// C[64,128] += A[64,256] @ B[256,128]; grid (16 m, 4 pair, 4 kc) = 256 blocks
__global__ void __launch_bounds__(256) k_agg()
{
    extern __shared__ float smx[];
    float* As = smx;                // [2][64*36]
    float* Bs = smx + 2*64*36;      // [2][128*36]
    int t = threadIdx.x;
    int i0 = blockIdx.x * 64;
    int y = blockIdx.y;
    int s = 1 + (y >> 1), b = y & 1;
    int kc = blockIdx.z;            // 0..3, K=256 chunk
    size_t fb = ((size_t)s*2048 + b*1024)*Cc;
    const float* Asrc = (s == 1 ? d_adjm1 : d_adjm2) + (size_t)b*Nc*Nc;
    int warp = t >> 5, lane = t & 31;
    int wm = (warp >> 2)*32, wn = (warp & 3)*32;
    int lr = lane >> 2, lc = lane & 3;
    float acc[2][4][4];
    #pragma unroll
    for (int mi = 0; mi < 2; mi++)
        #pragma unroll
        for (int ni = 0; ni < 4; ni++)
            #pragma unroll
            for (int q = 0; q < 4; q++) acc[mi][ni][q] = 0.f;

    int am = t >> 2, ak0 = (t & 3)*8;
    int bj = t & 31, bc0 = (t >> 5)*16;
    const float* asrc0 = Asrc + (size_t)(i0 + am)*Nc + kc*256 + ak0;
    const float* bsrc0 = d_Xnbr + fb + (size_t)(kc*256 + bj)*Cc + bc0;

    float4 pa0 = *(const float4*)asrc0, pa1 = *(const float4*)(asrc0 + 4);
    float4 pb0 = *(const float4*)(bsrc0), pb1 = *(const float4*)(bsrc0 + 4),
           pb2 = *(const float4*)(bsrc0 + 8), pb3 = *(const float4*)(bsrc0 + 12);

    for (int ks = 0; ks < 256; ks += 32) {
        int buf = (ks >> 5) & 1;
        float* Ab = As + buf*(64*36);
        float* Bb = Bs + buf*(128*36);
        {   // store staged A into this stage's buffer
            float* dst = Ab + am*36 + ak0;
            dst[0] = __uint_as_float(f2tf32(pa0.x)); dst[1] = __uint_as_float(f2tf32(pa0.y));
            dst[2] = __uint_as_float(f2tf32(pa0.z)); dst[3] = __uint_as_float(f2tf32(pa0.w));
            dst[4] = __uint_as_float(f2tf32(pa1.x)); dst[5] = __uint_as_float(f2tf32(pa1.y));
            dst[6] = __uint_as_float(f2tf32(pa1.z)); dst[7] = __uint_as_float(f2tf32(pa1.w));
        }
        {   // store staged B (transposed)
            Bb[(bc0+ 0)*36 + bj] = __uint_as_float(f2tf32(pb0.x));
            Bb[(bc0+ 1)*36 + bj] = __uint_as_float(f2tf32(pb0.y));
            Bb[(bc0+ 2)*36 + bj] = __uint_as_float(f2tf32(pb0.z));
            Bb[(bc0+ 3)*36 + bj] = __uint_as_float(f2tf32(pb0.w));
            Bb[(bc0+ 4)*36 + bj] = __uint_as_float(f2tf32(pb1.x));
            Bb[(bc0+ 5)*36 + bj] = __uint_as_float(f2tf32(pb1.y));
            Bb[(bc0+ 6)*36 + bj] = __uint_as_float(f2tf32(pb1.z));
            Bb[(bc0+ 7)*36 + bj] = __uint_as_float(f2tf32(pb1.w));
            Bb[(bc0+ 8)*36 + bj] = __uint_as_float(f2tf32(pb2.x));
            Bb[(bc0+ 9)*36 + bj] = __uint_as_float(f2tf32(pb2.y));
            Bb[(bc0+10)*36 + bj] = __uint_as_float(f2tf32(pb2.z));
            Bb[(bc0+11)*36 + bj] = __uint_as_float(f2tf32(pb2.w));
            Bb[(bc0+12)*36 + bj] = __uint_as_float(f2tf32(pb3.x));
            Bb[(bc0+13)*36 + bj] = __uint_as_float(f2tf32(pb3.y));
            Bb[(bc0+14)*36 + bj] = __uint_as_float(f2tf32(pb3.z));
            Bb[(bc0+15)*36 + bj] = __uint_as_float(f2tf32(pb3.w));
        }
        __syncthreads();
        if (ks < 224) {   // prefetch next stage; latency hides behind MMAs
            pa0 = *(const float4*)(asrc0 + ks + 32);
            pa1 = *(const float4*)(asrc0 + ks + 36);
            const float* bn = bsrc0 + (size_t)(ks + 32)*Cc;
            pb0 = *(const float4*)(bn); pb1 = *(const float4*)(bn + 4);
            pb2 = *(const float4*)(bn + 8); pb3 = *(const float4*)(bn + 12);
        }
        #pragma unroll
        for (int k8 = 0; k8 < 32; k8 += 8) {
            uint32_t afr[2][4];
            #pragma unroll
            for (int mi = 0; mi < 2; mi++) {
                int r = wm + mi*16 + lr;
                afr[mi][0] = __float_as_uint(Ab[(r  )*36 + k8 + lc    ]);
                afr[mi][1] = __float_as_uint(Ab[(r+8)*36 + k8 + lc    ]);
                afr[mi][2] = __float_as_uint(Ab[(r  )*36 + k8 + lc + 4]);
                afr[mi][3] = __float_as_uint(Ab[(r+8)*36 + k8 + lc + 4]);
            }
            uint32_t bfr[4][2];
            #pragma unroll
            for (int ni = 0; ni < 4; ni++) {
                int n = wn + ni*8 + lr;
                bfr[ni][0] = __float_as_uint(Bb[n*36 + k8 + lc    ]);
                bfr[ni][1] = __float_as_uint(Bb[n*36 + k8 + lc + 4]);
            }
            #pragma unroll
            for (int mi = 0; mi < 2; mi++)
                #pragma unroll
                for (int ni = 0; ni < 4; ni++)
                    mma_tf32(acc[mi][ni], afr[mi], bfr[ni]);
        }
    }
    size_t pb = (size_t)y*524288 + (size_t)kc*131072;
    #pragma unroll
    for (int mi = 0; mi < 2; mi++) {
        #pragma unroll
        for (int ni = 0; ni < 4; ni++) {
            int r0 = i0 + wm + mi*16 + lr;
            int col = wn + ni*8 + lc*2;
            *(float2*)&d_convp[pb + (size_t)r0*Cc + col]
                = make_float2(acc[mi][ni][0], acc[mi][ni][1]);
            *(float2*)&d_convp[pb + (size_t)(r0+8)*Cc + col]
                = make_float2(acc[mi][ni][2], acc[mi][ni][3]);
        }
    }
}

// ==================== combine partials + BN partial stats (+ s=0 diag agg) ====================
// grid (3, 128), 128 threads; each part covers 16 rows; 4 kc partials
__global__ void k_comb()
{
    int s = blockIdx.x, part = blockIdx.y, t = threadIdx.x;
    float su = 0.f, sq = 0.f;
    int rbase = part*16;
    if (s == 0) {
        __shared__ float Xn[16][129];
        __shared__ float Am[16][17];
        int b = rbase >> 10, n0 = rbase & 1023;
        #pragma unroll
        for (int j2 = 0; j2 < 16; j2++)
            Xn[j2][t] = d_Xnbr[((size_t)b*1024 + n0 + j2)*Cc + t];
        #pragma unroll
        for (int l = 0; l < 2; l++) {
            int id = t + l*128;
            int i = id >> 4, j = id & 15;
            Am[i][j] = d_diagm[b*16384 + (n0 + i)*16 + j];
        }
        __syncthreads();
        for (int r0 = 0; r0 < 16; r0++) {
            int rr = rbase + r0;
            size_t ci = (size_t)rr*Cc + t;
            float v = d_Xroot[ci];
            #pragma unroll
            for (int j = 0; j < 16; j++)
                v = fmaf(Am[r0][j], Xn[j][t], v);
            d_conv[ci] = v;
            su += v; sq = fmaf(v, v, sq);
        }
    } else {
        for (int r0 = 0; r0 < 16; r0++) {
            int rr = rbase + r0;
            size_t ci = ((size_t)s*2048 + rr)*Cc + t;
            int b = rr >> 10, n = rr & 1023;
            size_t pbb = ((size_t)(s-1)*2 + b)*524288 + (size_t)n*Cc + t;
            float v = d_Xroot[ci] + d_convp[pbb] + d_convp[pbb + 131072]
                    + d_convp[pbb + 262144] + d_convp[pbb + 393216];
            d_conv[ci] = v;
            su += v; sq = fmaf(v, v, sq);
        }
    }
    d_psum[(s*128 + part)*Cc + t] = su;
    d_psq [(s*128 + part)*Cc + t] = sq;
}

// ==================== att GEMM ====================
__global__ void __launch_bounds__(256) k_attgemm(const float* __restrict__ attW, const float* __restrict__ attb,
                          const float* __restrict__ gamma, const float* __restrict__ beta)
{
    extern __shared__ float sm[];
    float* Xs = sm;
    float* Ws = sm + 2*32*68;
    float* scl = sm + 12800;
    float* sft = scl + 128;
    int t = threadIdx.x;
    int row0 = blockIdx.x * 64;
    int s = row0 >> 11;
    if (t < 128) {
        float su = 0.f, sq = 0.f;
        #pragma unroll 8
        for (int p = 0; p < 128; p++) {
            su += d_psum[(s*128+p)*Cc + t];
            sq += d_psq [(s*128+p)*Cc + t];
        }
        float mu = su / 2048.f;
        float va = sq / 2048.f - mu*mu;
        float sc = gamma[s*Cc + t]*rsqrtf(va + 1e-5f);
        scl[t] = sc;
        sft[t] = beta[s*Cc + t] - mu*sc;
    }
    __syncthreads();
    const float* Wp = attW + s*Cc*Cc;
    int xr = t >> 2, xk = (t & 3)*8;
    int wk = t >> 3, wc = (t & 7)*16;
    int fr = (row0 + xr) & 2047;
    const float* cg = d_conv + (size_t)(row0 + xr)*Cc + xk;
    const float* fg = d_feats + (size_t)fr*Cc + xk;
    const float* wg = Wp + (size_t)wk*Cc + wc;
    {
        float4 c0 = *(const float4*)cg, c1 = *(const float4*)(cg+4);
        float4 f0 = *(const float4*)fg, f1 = *(const float4*)(fg+4);
        float* xd = Xs + xr;
        xd[(xk+0)*68] = c0.x*scl[xk+0]+sft[xk+0]+f0.x;
        xd[(xk+1)*68] = c0.y*scl[xk+1]+sft[xk+1]+f0.y;
        xd[(xk+2)*68] = c0.z*scl[xk+2]+sft[xk+2]+f0.z;
        xd[(xk+3)*68] = c0.w*scl[xk+3]+sft[xk+3]+f0.w;
        xd[(xk+4)*68] = c1.x*scl[xk+4]+sft[xk+4]+f1.x;
        xd[(xk+5)*68] = c1.y*scl[xk+5]+sft[xk+5]+f1.y;
        xd[(xk+6)*68] = c1.z*scl[xk+6]+sft[xk+6]+f1.z;
        xd[(xk+7)*68] = c1.w*scl[xk+7]+sft[xk+7]+f1.w;
        float* wd = Ws + wk*132 + wc;
        *(float4*)(wd  ) = *(const float4*)(wg  );
        *(float4*)(wd+4) = *(const float4*)(wg+4);
        *(float4*)(wd+8) = *(const float4*)(wg+8);
        *(float4*)(wd+12)= *(const float4*)(wg+12);
    }
    __syncthreads();
    int tx = t & 31, ty = t >> 5;
    float acc[8][4] = {};
    #pragma unroll
    for (int kb = 0; kb < 4; kb++) {
        int buf = kb & 1;
        float4 pc0, pc1, pf0, pf1, pw0, pw1, pw2, pw3;
        if (kb < 3) {
            pc0 = *(const float4*)(cg + (kb+1)*32);
            pc1 = *(const float4*)(cg + (kb+1)*32 + 4);
            pf0 = *(const float4*)(fg + (kb+1)*32);
            pf1 = *(const float4*)(fg + (kb+1)*32 + 4);
            const float* wn = wg + (size_t)(kb+1)*32*Cc;
            pw0 = *(const float4*)(wn); pw1 = *(const float4*)(wn+4);
            pw2 = *(const float4*)(wn+8); pw3 = *(const float4*)(wn+12);
        }
        const float* Xb = Xs + buf*(32*68);
        const float* Wb = Ws + buf*(32*132);
        #pragma unroll
        for (int k = 0; k < 32; k++) {
            float4 a0 = *(const float4*)&Xb[k*68 + ty*8];
            float4 a1 = *(const float4*)&Xb[k*68 + ty*8 + 4];
            float4 bv = *(const float4*)&Wb[k*132 + tx*4];
            float aa[8] = {a0.x,a0.y,a0.z,a0.w,a1.x,a1.y,a1.z,a1.w};
            float bb[4] = {bv.x,bv.y,bv.z,bv.w};
            #pragma unroll
            for (int i = 0; i < 8; i++)
                #pragma unroll
                for (int j = 0; j < 4; j++)
                    acc[i][j] = fmaf(aa[i], bb[j], acc[i][j]);
        }
        if (kb < 3) {
            int nb = buf ^ 1;
            int kbase = (kb+1)*32;
            float* xd = Xs + nb*(32*68) + xr;
            xd[(xk+0)*68] = pc0.x*scl[kbase+xk+0]+sft[kbase+xk+0]+pf0.x;
            xd[(xk+1)*68] = pc0.y*scl[kbase+xk+1]+sft[kbase+xk+1]+pf0.y;
            xd[(xk+2)*68] = pc0.z*scl[kbase+xk+2]+sft[kbase+xk+2]+pf0.z;
            xd[(xk+3)*68] = pc0.w*scl[kbase+xk+3]+sft[kbase+xk+3]+pf0.w;
            xd[(xk+4)*68] = pc1.x*scl[kbase+xk+4]+sft[kbase+xk+4]+pf1.x;
            xd[(xk+5)*68] = pc1.y*scl[kbase+xk+5]+sft[kbase+xk+5]+pf1.y;
            xd[(xk+6)*68] = pc1.z*scl[kbase+xk+6]+sft[kbase+xk+6]+pf1.z;
            xd[(xk+7)*68] = pc1.w*scl[kbase+xk+7]+sft[kbase+xk+7]+pf1.w;
            float* wd = Ws + nb*(32*132) + wk*132 + wc;
            *(float4*)(wd  ) = pw0; *(float4*)(wd+4) = pw1;
            *(float4*)(wd+8) = pw2; *(float4*)(wd+12)= pw3;
            __syncthreads();
        }
    }
    float colmax[4] = {-3.4e38f,-3.4e38f,-3.4e38f,-3.4e38f};
    #pragma unroll
    for (int i = 0; i < 8; i++) {
        int row = row0 + ty*8 + i;
        int frr = row & 2047;
        float4 cv = *(const float4*)&d_conv[(size_t)row*Cc + tx*4];
        float4 fv = *(const float4*)&d_feats[(size_t)frr*Cc + tx*4];
        float cva[4] = {cv.x,cv.y,cv.z,cv.w};
        float fva[4] = {fv.x,fv.y,fv.z,fv.w};
        float o[4];
        #pragma unroll
        for (int j = 0; j < 4; j++) {
            int c = tx*4 + j;
            float v = acc[i][j] + attb[s*Cc + c];
            float hv = cva[j]*scl[c] + sft[c] + fva[j];
            float yv = fmaxf(sigf(v)*hv, 0.f);
            o[j] = yv;
            colmax[j] = fmaxf(colmax[j], yv);
        }
        *(float4*)&d_y[(size_t)row*Cc + tx*4] = make_float4(o[0],o[1],o[2],o[3]);
    }
    __syncthreads();
    float* pm = sm;
    #pragma unroll
    for (int j = 0; j < 4; j++) pm[ty*132 + tx*4 + j] = colmax[j];
    __syncthreads();
    if (t < 128) {
        float m = -3.4e38f;
        #pragma unroll
        for (int q = 0; q < 8; q++) m = fmaxf(m, pm[q*132 + t]);
        int bb = (row0 >> 10) & 1, tl = (row0 & 1023) >> 6;
        d_poolp[((s*2 + bb)*16 + tl)*Cc + t] = m;
    }
}

// ==================== mlp ====================
__global__ void k_mlp(const float* __restrict__ W1, const float* __restrict__ b1,
                      const float* __restrict__ W2, const float* __restrict__ b2)
{
    int sb = blockIdx.x, t = threadIdx.x;
    int s = sb >> 1;
    __shared__ float p[128], t1[128];
    float m = -3.4e38f;
    #pragma unroll
    for (int ch = 0; ch < 16; ch++) m = fmaxf(m, d_poolp[(sb*16 + ch)*Cc + t]);
    p[t] = m;
    __syncthreads();
    float acc = b1[s*Cc + t];
    #pragma unroll 8
    for (int k = 0; k < 128; k++) acc = fmaf(p[k], W1[s*Cc*Cc + k*Cc + t], acc);
    t1[t] = fmaxf(acc, 0.f);
    __syncthreads();
    float acc2 = b2[s*Cc + t];
    #pragma unroll 8
    for (int k = 0; k < 128; k++) acc2 = fmaf(t1[k], W2[s*Cc*Cc + k*Cc + t], acc2);
    d_pools2[sb*Cc + t] = sigf(acc2);
}

// ==================== final GEMM: fused softmax-mix X + Aw prologue ====================
__global__ void __launch_bounds__(256) k_fusegemm(const float* __restrict__ W, const float* __restrict__ bias,
                           const float* __restrict__ lw, const float* __restrict__ lb)
{
    extern __shared__ float sm[];
    float* Xs = sm;
    float* Ws = sm + 2*32*68;
    float* p2s = sm + 12800;
    float* aw  = p2s + 384;
    int t = threadIdx.x;
    int row0 = blockIdx.x * 64;
    int b = row0 >> 10;
    for (int i = t; i < 384; i += 256)
        p2s[i] = d_pools2[((i >> 7)*2 + b)*Cc + (i & 127)];
    __syncthreads();
    if (t < 32) {
        float av[3];
        #pragma unroll
        for (int s = 0; s < 3; s++) {
            float r = 0.f;
            #pragma unroll
            for (int q = 0; q < 4; q++) {
                int c = t + q*32;
                r = fmaf(p2s[s*128 + c], lw[s*Cc + c], r);
            }
            #pragma unroll
            for (int o = 16; o; o >>= 1) r += __shfl_xor_sync(0xffffffffu, r, o);
            av[s] = r + lb[s];
        }
        if (t == 0) {
            float m = fmaxf(av[0], fmaxf(av[1], av[2]));
            float e0 = __expf(av[0]-m), e1 = __expf(av[1]-m), e2 = __expf(av[2]-m);
            float inv = 1.f/(e0+e1+e2);
            aw[0] = e0*inv; aw[1] = e1*inv; aw[2] = e2*inv;
        }
    }
    __syncthreads();
    float aw0 = aw[0], aw1 = aw[1], aw2 = aw[2];
    int xr = t >> 2, xk = (t & 3)*8;
    int wk = t >> 3, wc = (t & 7)*16;
    const float* y0 = d_y + (size_t)(row0 + xr)*Cc + xk;
    const float* y1 = y0 + (size_t)2048*Cc;
    const float* y2 = y1 + (size_t)2048*Cc;
    const float* wg = W + (size_t)wk*Cc + wc;
    #define FUSE_XLOAD(dst, off) { \
        float4 v0 = *(const float4*)(y0+(off)), v0b = *(const float4*)(y0+(off)+4); \
        float4 v1 = *(const float4*)(y1+(off)), v1b = *(const float4*)(y1+(off)+4); \
        float4 v2 = *(const float4*)(y2+(off)), v2b = *(const float4*)(y2+(off)+4); \
        int kb0 = (off) + xk; \
        dst[(xk+0)*68] = aw0*p2s[kb0+0]*v0.x + aw1*p2s[128+kb0+0]*v1.x + aw2*p2s[256+kb0+0]*v2.x; \
        dst[(xk+1)*68] = aw0*p2s[kb0+1]*v0.y + aw1*p2s[128+kb0+1]*v1.y + aw2*p2s[256+kb0+1]*v2.y; \
        dst[(xk+2)*68] = aw0*p2s[kb0+2]*v0.z + aw1*p2s[128+kb0+2]*v1.z + aw2*p2s[256+kb0+2]*v2.z; \
        dst[(xk+3)*68] = aw0*p2s[kb0+3]*v0.w + aw1*p2s[128+kb0+3]*v1.w + aw2*p2s[256+kb0+3]*v2.w; \
        dst[(xk+4)*68] = aw0*p2s[kb0+4]*v0b.x + aw1*p2s[128+kb0+4]*v1b.x + aw2*p2s[256+kb0+4]*v2b.x; \
        dst[(xk+5)*68] = aw0*p2s[kb0+5]*v0b.y + aw1*p2s[128+kb0+5]*v1b.y + aw2*p2s[256+kb0+5]*v2b.y; \
        dst[(xk+6)*68] = aw0*p2s[kb0+6]*v0b.z + aw1*p2s[128+kb0+6]*v1b.z + aw2*p2s[256+kb0+6]*v2b.z; \
        dst[(xk+7)*68] = aw0*p2s[kb0+7]*v0b.w + aw1*p2s[128+kb0+7]*v1b.w + aw2*p2s[256+kb0+7]*v2b.w; \
    }
    {
        float* xd = Xs + xr;
        FUSE_XLOAD(xd, 0);
        float* wd = Ws + wk*132 + wc;
        *(float4*)(wd  ) = *(const float4*)(wg  );
        *(float4*)(wd+4) = *(const float4*)(wg+4);
        *(float4*)(wd+8) = *(const float4*)(wg+8);
        *(float4*)(wd+12)= *(const float4*)(wg+12);
    }
    __syncthreads();
    int tx = t & 31, ty = t >> 5;
    float acc[8][4] = {};
    #pragma unroll
    for (int kb = 0; kb < 4; kb++) {
        int buf = kb & 1;
        const float* Xb = Xs + buf*(32*68);
        const float* Wb = Ws + buf*(32*132);
        #pragma unroll
        for (int k = 0; k < 32; k++) {
            float4 a0 = *(const float4*)&Xb[k*68 + ty*8];
            float4 a1 = *(const float4*)&Xb[k*68 + ty*8 + 4];
            float4 bv = *(const float4*)&Wb[k*132 + tx*4];
            float aa[8] = {a0.x,a0.y,a0.z,a0.w,a1.x,a1.y,a1.z,a1.w};
            float bb[4] = {bv.x,bv.y,bv.z,bv.w};
            #pragma unroll
            for (int i = 0; i < 8; i++)
                #pragma unroll
                for (int j = 0; j < 4; j++)
                    acc[i][j] = fmaf(aa[i], bb[j], acc[i][j]);
        }
        if (kb < 3) {
            __syncthreads();
            int nb = buf ^ 1;
            float* xd = Xs + nb*(32*68) + xr;
            FUSE_XLOAD(xd, (kb+1)*32);
            float* wd = Ws + nb*(32*132) + wk*132 + wc;
            const float* wn = wg + (size_t)(kb+1)*32*Cc;
            *(float4*)(wd  ) = *(const float4*)(wn  );
            *(float4*)(wd+4) = *(const float4*)(wn+4);
            *(float4*)(wd+8) = *(const float4*)(wn+8);
            *(float4*)(wd+12)= *(const float4*)(wn+12);
            __syncthreads();
        }
    }
    #pragma unroll
    for (int i = 0; i < 8; i++) {
        int r = row0 + ty*8 + i;
        float o[4];
        #pragma unroll
        for (int j = 0; j < 4; j++) o[j] = acc[i][j] + bias[tx*4 + j];
        *(float4*)&d_yfin[(size_t)r*Cc + tx*4] = make_float4(o[0],o[1],o[2],o[3]);
    }
}

// ==================== reprojection + residual ====================
__global__ void k_reproj(const float* __restrict__ x, float* __restrict__ out)
{
    __shared__ float yf[16*64];
    int blk = blockIdx.x, b = blockIdx.y, ch = blockIdx.z, t = threadIdx.x;
    int c0 = ch*64;
    #pragma unroll
    for (int l = 0; l < 4; l++) {
        int idx = t + l*256;
        yf[idx] = d_yfin[((size_t)b*1024 + blk*16 + (idx>>6))*Cc + c0 + (idx & 63)];
    }
    __syncthreads();
    float q[16];
    #pragma unroll
    for (int k = 0; k < 16; k++)
        q[k] = d_Q[(((size_t)b*NBLKc + blk)*BNODc + k)*NPc + t];
    int bi = blk >> 3, bj = blk & 7, hi = t >> 4, wi = t & 15;
    size_t base = (size_t)b*Cc*HWc + (size_t)c0*HWc + (size_t)(bi*16+hi)*Wc + (bj*16+wi);
    #pragma unroll 4
    for (int c4 = 0; c4 < 16; c4++) {
        float4 a = make_float4(0.f,0.f,0.f,0.f);
        #pragma unroll
        for (int k = 0; k < 16; k++) {
            float4 yv = *(float4*)&yf[k*64 + c4*4];
            a.x = fmaf(q[k], yv.x, a.x);
            a.y = fmaf(q[k], yv.y, a.y);
            a.z = fmaf(q[k], yv.z, a.z);
            a.w = fmaf(q[k], yv.w, a.w);
        }
        int c = c4*4;
        out[base + (size_t)(c+0)*HWc] = x[base + (size_t)(c+0)*HWc] + a.x;
        out[base + (size_t)(c+1)*HWc] = x[base + (size_t)(c+1)*HWc] + a.y;
        out[base + (size_t)(c+2)*HWc] = x[base + (size_t)(c+2)*HWc] + a.z;
        out[base + (size_t)(c+3)*HWc] = x[base + (size_t)(c+3)*HWc] + a.w;
    }
}

extern "C" void kernel_launch(void* const* d_in, const int* in_sizes, int n_in,
                              void* d_out, int out_size)
{
    const float* x        = (const float*)d_in[0];
    const float* anchor   = (const float*)d_in[1];
    const float* sigma    = (const float*)d_in[2];
    const float* W_root   = (const float*)d_in[3];
    const float* W_nbr    = (const float*)d_in[4];
    const float* wg_src   = (const float*)d_in[5];
    const float* wg_dst   = (const float*)d_in[6];
    const float* b_gate   = (const float*)d_in[7];
    const float* bn_gamma = (const float*)d_in[8];
    const float* bn_beta  = (const float*)d_in[9];
    const float* att_W    = (const float*)d_in[10];
    const float* att_b    = (const float*)d_in[11];
    const float* mlp_W1   = (const float*)d_in[12];
    const float* mlp_b1   = (const float*)d_in[13];
    const float* mlp_W2   = (const float*)d_in[14];
    const float* mlp_b2   = (const float*)d_in[15];
    const float* lineA_w  = (const float*)d_in[16];
    const float* lineA_b  = (const float*)d_in[17];
    const float* lineFu_W = (const float*)d_in[18];
    const float* lineFu_b = (const float*)d_in[19];
    float* out = (float*)d_out;

    cudaFuncSetAttribute(k_proj,     cudaFuncAttributeMaxDynamicSharedMemorySize, PROJ_SMEM);
    cudaFuncSetAttribute(k_gemm2,    cudaFuncAttributeMaxDynamicSharedMemorySize, G64_SMEM);
    cudaFuncSetAttribute(k_agg,      cudaFuncAttributeMaxDynamicSharedMemorySize, AGG_SMEM);
    cudaFuncSetAttribute(k_attgemm,  cudaFuncAttributeMaxDynamicSharedMemorySize, ATT_SMEM);
    cudaFuncSetAttribute(k_fusegemm, cudaFuncAttributeMaxDynamicSharedMemorySize, FUSE_SMEM);

    k_proj<<<dim3(NBLKc, Bc), 256, PROJ_SMEM>>>(x, anchor, sigma, wg_src, wg_dst, b_gate);
    k_adj<<<dim3(8, 16, Bc), 256>>>();
    k_gemm2<<<dim3(32, 6), 256, G64_SMEM>>>(W_root, W_nbr);
    k_agg<<<dim3(16, 4, 4), 256, AGG_SMEM>>>();
    k_comb<<<dim3(3, 128), 128>>>();
    k_attgemm<<<96, 256, ATT_SMEM>>>(att_W, att_b, bn_gamma, bn_beta);
    k_mlp<<<6, 128>>>(mlp_W1, mlp_b1, mlp_W2, mlp_b2);
    k_fusegemm<<<32, 256, FUSE_SMEM>>>(lineFu_W, lineFu_b, lineA_w, lineA_b);
    k_reproj<<<dim3(NBLKc, Bc, 2), 256>>>(x, out);
}